// round 1
// baseline (speedup 1.0000x reference)
#include <cuda_runtime.h>
#include <math.h>

// Problem constants
#define B   4
#define CIN 256
#define C   128
#define HW  64
#define N   4096          // HW*HW
#define CQK 16

// ---------------- scratch (device globals; no allocation) ----------------
__device__ float g_y[B * C * N];        // conv out, then feat (in-place) : 8 MB
__device__ float g_scale[C];
__device__ float g_shift[C];
__device__ float g_q[B * CQK * N];
__device__ float g_k[B * CQK * N];
__device__ float g_v[B * C * N];        // 8 MB
__device__ float g_e[B * C * C];        // CAM energy -> attn (in place)

// ---------------- K1: 3x3 conv, stride 1, pad 1 ----------------
// block: 256 thr; computes 32x32 output pixels x 8 output channels.
// grid: (2, 2, B*16)   z = b*16 + co_tile
__global__ void conv_kernel(const float* __restrict__ x, const float* __restrict__ w) {
    const int b   = blockIdx.z >> 4;
    const int co0 = (blockIdx.z & 15) * 8;
    const int ty0 = blockIdx.y * 32;
    const int tx0 = blockIdx.x * 32;
    const int t   = threadIdx.x;
    const int py  = (t >> 4) * 2;   // local pixel row base (0..30)
    const int px  = (t & 15) * 2;   // local pixel col base

    __shared__ float xs[34 * 36];   // 34x34 halo tile, pitch 36
    __shared__ float ws[8 * 9];

    float acc[8][2][2];
#pragma unroll
    for (int o = 0; o < 8; o++)
#pragma unroll
        for (int r = 0; r < 2; r++)
#pragma unroll
            for (int c2 = 0; c2 < 2; c2++) acc[o][r][c2] = 0.f;

    for (int ci = 0; ci < CIN; ci++) {
        // load halo tile
        for (int i = t; i < 34 * 34; i += 256) {
            int r = i / 34, cc = i % 34;
            int gy = ty0 - 1 + r, gx = tx0 - 1 + cc;
            float v = 0.f;
            if (gy >= 0 && gy < HW && gx >= 0 && gx < HW)
                v = x[(((b * CIN + ci) << 6) + gy) * 64 + gx];
            xs[r * 36 + cc] = v;
        }
        if (t < 72) ws[t] = w[((co0 + t / 9) * CIN + ci) * 9 + (t % 9)];
        __syncthreads();

        float xv[4][4];
#pragma unroll
        for (int r = 0; r < 4; r++)
#pragma unroll
            for (int c2 = 0; c2 < 4; c2++)
                xv[r][c2] = xs[(py + r) * 36 + px + c2];

#pragma unroll
        for (int o = 0; o < 8; o++) {
#pragma unroll
            for (int ky = 0; ky < 3; ky++)
#pragma unroll
                for (int kx = 0; kx < 3; kx++) {
                    float wv = ws[o * 9 + ky * 3 + kx];
                    acc[o][0][0] += xv[ky][kx]     * wv;
                    acc[o][0][1] += xv[ky][kx + 1] * wv;
                    acc[o][1][0] += xv[ky + 1][kx]     * wv;
                    acc[o][1][1] += xv[ky + 1][kx + 1] * wv;
                }
        }
        __syncthreads();
    }
#pragma unroll
    for (int o = 0; o < 8; o++)
#pragma unroll
        for (int r = 0; r < 2; r++)
#pragma unroll
            for (int c2 = 0; c2 < 2; c2++)
                g_y[((b * C + co0 + o) << 12) + ((ty0 + py + r) << 6) + tx0 + px + c2] =
                    acc[o][r][c2];
}

// ---------------- K2: per-channel batch stats -> scale/shift ----------------
__global__ void bnstats_kernel(const float* __restrict__ gamma, const float* __restrict__ beta) {
    const int c = blockIdx.x;
    const int t = threadIdx.x;
    float s = 0.f, ss = 0.f;
    for (int i = t; i < B * N; i += 256) {
        int b = i >> 12, n = i & 4095;
        float v = g_y[((b * C + c) << 12) + n];
        s += v; ss += v * v;
    }
    __shared__ float r1[256], r2[256];
    r1[t] = s; r2[t] = ss;
    __syncthreads();
    for (int off = 128; off; off >>= 1) {
        if (t < off) { r1[t] += r1[t + off]; r2[t] += r2[t + off]; }
        __syncthreads();
    }
    if (t == 0) {
        const float inv = 1.f / (float)(B * N);
        float mean = r1[0] * inv;
        float var  = r2[0] * inv - mean * mean;
        float istd = rsqrtf(var + 1e-5f);
        float sc = gamma[c] * istd;
        g_scale[c] = sc;
        g_shift[c] = beta[c] - mean * sc;
    }
}

// ---------------- K3: BN + ReLU (in place) and d_out = 3*feat ----------------
__global__ void bnrelu_kernel(float* __restrict__ out) {
    const int total = B * C * N;
    for (int i = blockIdx.x * 256 + threadIdx.x; i < total; i += 2048 * 256) {
        int c = (i >> 12) & (C - 1);
        float v = fmaxf(g_y[i] * g_scale[c] + g_shift[c], 0.f);
        g_y[i] = v;
        out[i] = 3.f * v;
    }
}

// ---------------- K4: fused q/k/v projection (160 x 128 GEMM over N) ----------
// grid (64, B); block 256: n-tile of 64, thread = (og 0..15) x (n-quad 0..15), 10 outs each
__global__ void qkv_kernel(const float* __restrict__ qw, const float* __restrict__ qb,
                           const float* __restrict__ kw, const float* __restrict__ kb,
                           const float* __restrict__ vw, const float* __restrict__ vb) {
    const int b = blockIdx.y, n0 = blockIdx.x * 64;
    const int t = threadIdx.x;
    __shared__ float Wc[160 * 33];
    __shared__ float fs[32 * 64];
    __shared__ float bias_s[160];
    if (t < 160) bias_s[t] = (t < 16) ? qb[t] : (t < 32 ? kb[t - 16] : vb[t - 32]);
    const int og = t >> 4, nl = (t & 15) * 4;

    float4 acc[10];
#pragma unroll
    for (int j = 0; j < 10; j++) acc[j] = make_float4(0.f, 0.f, 0.f, 0.f);

    for (int cc = 0; cc < C; cc += 32) {
        for (int i = t; i < 160 * 32; i += 256) {
            int o = i >> 5, c = i & 31;
            float wv = (o < 16) ? qw[o * C + cc + c]
                     : (o < 32) ? kw[(o - 16) * C + cc + c]
                                : vw[(o - 32) * C + cc + c];
            Wc[o * 33 + c] = wv;
        }
        for (int i = t; i < 2048; i += 256) {
            int c = i >> 6, n = i & 63;
            fs[c * 64 + n] = g_y[((b * C + cc + c) << 12) + n0 + n];
        }
        __syncthreads();
#pragma unroll
        for (int c = 0; c < 32; c++) {
            float4 fv = *(const float4*)&fs[c * 64 + nl];
#pragma unroll
            for (int j = 0; j < 10; j++) {
                float wv = Wc[(og * 10 + j) * 33 + c];
                acc[j].x += wv * fv.x; acc[j].y += wv * fv.y;
                acc[j].z += wv * fv.z; acc[j].w += wv * fv.w;
            }
        }
        __syncthreads();
    }
#pragma unroll
    for (int j = 0; j < 10; j++) {
        int o = og * 10 + j;
        float bi = bias_s[o];
        acc[j].x += bi; acc[j].y += bi; acc[j].z += bi; acc[j].w += bi;
        float* dst = (o < 16) ? &g_q[(b * CQK + o) << 12]
                   : (o < 32) ? &g_k[(b * CQK + o - 16) << 12]
                              : &g_v[(b * C + o - 32) << 12];
        *(float4*)&dst[n0 + nl] = acc[j];
    }
}

// ---------------- K5: CAM energy  e[c][d] = sum_n f[c][n] f[d][n] -------------
// grid (16, B): 4x4 tiles of 32x32; block 256, 2x2 per thread.
__global__ void cam_energy_kernel() {
    const int b = blockIdx.y;
    const int c0 = (blockIdx.x >> 2) * 32, d0 = (blockIdx.x & 3) * 32;
    const int t = threadIdx.x;
    const int lc = (t >> 4) * 2, ld = 32 + (t & 15) * 2;
    __shared__ float fs[64 * 33];    // rows 0..31 = c-block, 32..63 = d-block
    float acc[2][2] = {{0.f, 0.f}, {0.f, 0.f}};

    for (int n0 = 0; n0 < N; n0 += 32) {
        for (int i = t; i < 2048; i += 256) {
            int r = i >> 5, n = i & 31;
            int ch = (r < 32) ? (c0 + r) : (d0 + r - 32);
            fs[r * 33 + n] = g_y[((b * C + ch) << 12) + n0 + n];
        }
        __syncthreads();
#pragma unroll
        for (int n = 0; n < 32; n++) {
            float a0 = fs[lc * 33 + n],       a1 = fs[(lc + 1) * 33 + n];
            float b0 = fs[ld * 33 + n],       b1 = fs[(ld + 1) * 33 + n];
            acc[0][0] += a0 * b0; acc[0][1] += a0 * b1;
            acc[1][0] += a1 * b0; acc[1][1] += a1 * b1;
        }
        __syncthreads();
    }
#pragma unroll
    for (int i = 0; i < 2; i++)
#pragma unroll
        for (int j = 0; j < 2; j++)
            g_e[(b * C + c0 + lc + i) * C + d0 + (ld - 32) + j] = acc[i][j];
}

// ---------------- K6: CAM attn = tanh(rowmax - e), in place ------------------
__global__ void cam_attn_kernel() {
    const int b = blockIdx.y, c = blockIdx.x, t = threadIdx.x; // 128 threads
    float v = g_e[((b * C + c) << 7) + t];
    __shared__ float red[128];
    red[t] = v;
    __syncthreads();
    for (int off = 64; off; off >>= 1) {
        if (t < off) red[t] = fmaxf(red[t], red[t + off]);
        __syncthreads();
    }
    g_e[((b * C + c) << 7) + t] = tanhf(red[0] - v);
}

// ---------------- K7: CAM out: d_out += gamma_ca * (attn @ f) ----------------
// grid (64, B); block 256, thread = (og 0..15) x (n-quad), 8 outs each
__global__ void cam_out_kernel(const float* __restrict__ gca, float* __restrict__ out) {
    const int b = blockIdx.y, n0 = blockIdx.x * 64;
    const int t = threadIdx.x;
    __shared__ float At[128 * 33];
    __shared__ float fs[32 * 64];
    const int og = t >> 4, nl = (t & 15) * 4;

    float4 acc[8];
#pragma unroll
    for (int j = 0; j < 8; j++) acc[j] = make_float4(0.f, 0.f, 0.f, 0.f);

    for (int dc = 0; dc < C; dc += 32) {
        for (int i = t; i < 128 * 32; i += 256) {
            int o = i >> 5, d = i & 31;
            At[o * 33 + d] = g_e[((b * C + o) << 7) + dc + d];
        }
        for (int i = t; i < 2048; i += 256) {
            int d = i >> 6, n = i & 63;
            fs[d * 64 + n] = g_y[((b * C + dc + d) << 12) + n0 + n];
        }
        __syncthreads();
#pragma unroll
        for (int d = 0; d < 32; d++) {
            float4 fv = *(const float4*)&fs[d * 64 + nl];
#pragma unroll
            for (int j = 0; j < 8; j++) {
                float wv = At[(og * 8 + j) * 33 + d];
                acc[j].x += wv * fv.x; acc[j].y += wv * fv.y;
                acc[j].z += wv * fv.z; acc[j].w += wv * fv.w;
            }
        }
        __syncthreads();
    }
    const float g = gca[0];
#pragma unroll
    for (int j = 0; j < 8; j++) {
        int o = og * 8 + j;
        float4* dp = (float4*)&out[((b * C + o) << 12) + n0 + nl];
        float4 cur = *dp;
        cur.x += g * acc[j].x; cur.y += g * acc[j].y;
        cur.z += g * acc[j].z; cur.w += g * acc[j].w;
        *dp = cur;
    }
}

// ---------------- K8: PAM flash: d_out += gamma_pa * (v @ tanh(q^T k)^T) -----
// out[c][m] = sum_n v[c][n] * tanh(sum_q q[q][m] k[q][n])
// grid (64, B): m-tile of 64; block 256; acc = 4m x 8c per thread; n chunk 32.
__global__ void pam_kernel(const float* __restrict__ gpa, float* __restrict__ out) {
    const int b = blockIdx.y, m0 = blockIdx.x * 64;
    const int t = threadIdx.x;
    __shared__ float qs[16 * 64];
    __shared__ float ks[16 * 32];
    __shared__ float vs[128 * 33];
    __shared__ float Ss[32 * 64];   // transposed: Ss[n][m]

    for (int i = t; i < 1024; i += 256) {
        int qc = i >> 6, m = i & 63;
        qs[qc * 64 + m] = g_q[((b * CQK + qc) << 12) + m0 + m];
    }
    __syncthreads();

    const int mq = (t & 15) * 4, cg = t >> 4;       // acc-phase mapping
    const int sm = t & 63, snb = (t >> 6) * 8;      // S-phase mapping
    float qv[16];
#pragma unroll
    for (int qc = 0; qc < 16; qc++) qv[qc] = qs[qc * 64 + sm];

    float acc[4][8];
#pragma unroll
    for (int i = 0; i < 4; i++)
#pragma unroll
        for (int j = 0; j < 8; j++) acc[i][j] = 0.f;

    for (int n0 = 0; n0 < N; n0 += 32) {
        for (int i = t; i < 512; i += 256) {
            int qc = i >> 5, n = i & 31;
            ks[qc * 32 + n] = g_k[((b * CQK + qc) << 12) + n0 + n];
        }
        for (int i = t; i < 4096; i += 256) {
            int c = i >> 5, n = i & 31;
            vs[c * 33 + n] = g_v[((b * C + c) << 12) + n0 + n];
        }
        __syncthreads();
        // S phase: S[m][n] = tanh(sum_q q[q][m]*k[q][n]); stored transposed
#pragma unroll
        for (int j = 0; j < 8; j++) {
            int n = snb + j;
            float s = 0.f;
#pragma unroll
            for (int qc = 0; qc < 16; qc++) s += qv[qc] * ks[qc * 32 + n];
            Ss[n * 64 + sm] = tanhf(s);
        }
        __syncthreads();
        // accumulate phase
#pragma unroll
        for (int n = 0; n < 32; n++) {
            float4 s4 = *(const float4*)&Ss[n * 64 + mq];
#pragma unroll
            for (int j = 0; j < 8; j++) {
                float vvv = vs[(cg * 8 + j) * 33 + n];
                acc[0][j] += s4.x * vvv; acc[1][j] += s4.y * vvv;
                acc[2][j] += s4.z * vvv; acc[3][j] += s4.w * vvv;
            }
        }
        __syncthreads();
    }
    const float g = gpa[0];
#pragma unroll
    for (int j = 0; j < 8; j++) {
        int c = cg * 8 + j;
#pragma unroll
        for (int i = 0; i < 4; i++) {
            float* p = &out[((b * C + c) << 12) + m0 + mq + i];
            *p += g * acc[i][j];
        }
    }
}

// ---------------- launch ----------------
extern "C" void kernel_launch(void* const* d_in, const int* in_sizes, int n_in,
                              void* d_out, int out_size) {
    const float* x       = (const float*)d_in[0];
    const float* conv_w  = (const float*)d_in[1];
    const float* bn_g    = (const float*)d_in[2];
    const float* bn_b    = (const float*)d_in[3];
    const float* q_w     = (const float*)d_in[4];
    const float* q_b     = (const float*)d_in[5];
    const float* k_w     = (const float*)d_in[6];
    const float* k_b     = (const float*)d_in[7];
    const float* v_w     = (const float*)d_in[8];
    const float* v_b     = (const float*)d_in[9];
    const float* gca     = (const float*)d_in[10];
    const float* gpa     = (const float*)d_in[11];
    float* out = (float*)d_out;

    conv_kernel<<<dim3(2, 2, B * 16), 256>>>(x, conv_w);
    bnstats_kernel<<<C, 256>>>(bn_g, bn_b);
    bnrelu_kernel<<<2048, 256>>>(out);
    qkv_kernel<<<dim3(64, B), 256>>>(q_w, q_b, k_w, k_b, v_w, v_b);
    cam_energy_kernel<<<dim3(16, B), 256>>>();
    cam_attn_kernel<<<dim3(C, B), 128>>>();
    cam_out_kernel<<<dim3(64, B), 256>>>(gca, out);
    pam_kernel<<<dim3(64, B), 256>>>(gpa, out);
}

// round 3
// speedup vs baseline: 1.4323x; 1.4323x over previous
#include <cuda_runtime.h>
#include <math.h>
#include <stdint.h>

// Problem constants
#define B   4
#define CIN 256
#define C   128
#define HW  64
#define N   4096          // HW*HW
#define CQK 16

// ---------------- scratch (device globals; no allocation) ----------------
__device__ float g_y[B * C * N];        // conv out, then feat (in-place) : 8 MB
__device__ float g_scale[C];
__device__ float g_shift[C];
__device__ float g_q[B * CQK * N];
__device__ float g_k[B * CQK * N];
__device__ float g_v[B * C * N];        // 8 MB
__device__ float g_e[B * C * C];        // CAM energy -> attn (in place)

// ================= base-ISA tensor helpers (NO tcgen05 — plain sm_103) ======
__device__ __forceinline__ uint32_t f32_tf32(float f) {
    uint32_t r;
    asm("cvt.rna.tf32.f32 %0, %1;" : "=r"(r) : "f"(f));
    return r;
}
__device__ __forceinline__ float tanh_ap(float x) {
    float y;
    asm("tanh.approx.f32 %0, %1;" : "=f"(y) : "f"(x));
    return y;
}
// D += A(16x8 tf32) * B(8x8 tf32), fp32 accum
__device__ __forceinline__ void mma_tf32(float* d, const uint32_t* a, uint32_t b0, uint32_t b1) {
    asm volatile(
        "mma.sync.aligned.m16n8k8.row.col.f32.tf32.tf32.f32 "
        "{%0,%1,%2,%3}, {%4,%5,%6,%7}, {%8,%9}, {%0,%1,%2,%3};"
        : "+f"(d[0]), "+f"(d[1]), "+f"(d[2]), "+f"(d[3])
        : "r"(a[0]), "r"(a[1]), "r"(a[2]), "r"(a[3]), "r"(b0), "r"(b1));
}

// ---------------- K1: 3x3 conv, stride 1, pad 1 ----------------
__global__ void conv_kernel(const float* __restrict__ x, const float* __restrict__ w) {
    const int b   = blockIdx.z >> 4;
    const int co0 = (blockIdx.z & 15) * 8;
    const int ty0 = blockIdx.y * 32;
    const int tx0 = blockIdx.x * 32;
    const int t   = threadIdx.x;
    const int py  = (t >> 4) * 2;
    const int px  = (t & 15) * 2;

    __shared__ float xs[34 * 36];
    __shared__ float ws[8 * 9];

    float acc[8][2][2];
#pragma unroll
    for (int o = 0; o < 8; o++)
#pragma unroll
        for (int r = 0; r < 2; r++)
#pragma unroll
            for (int c2 = 0; c2 < 2; c2++) acc[o][r][c2] = 0.f;

    for (int ci = 0; ci < CIN; ci++) {
        for (int i = t; i < 34 * 34; i += 256) {
            int r = i / 34, cc = i % 34;
            int gy = ty0 - 1 + r, gx = tx0 - 1 + cc;
            float v = 0.f;
            if (gy >= 0 && gy < HW && gx >= 0 && gx < HW)
                v = x[(((b * CIN + ci) << 6) + gy) * 64 + gx];
            xs[r * 36 + cc] = v;
        }
        if (t < 72) ws[t] = w[((co0 + t / 9) * CIN + ci) * 9 + (t % 9)];
        __syncthreads();

        float xv[4][4];
#pragma unroll
        for (int r = 0; r < 4; r++)
#pragma unroll
            for (int c2 = 0; c2 < 4; c2++)
                xv[r][c2] = xs[(py + r) * 36 + px + c2];

#pragma unroll
        for (int o = 0; o < 8; o++) {
#pragma unroll
            for (int ky = 0; ky < 3; ky++)
#pragma unroll
                for (int kx = 0; kx < 3; kx++) {
                    float wv = ws[o * 9 + ky * 3 + kx];
                    acc[o][0][0] += xv[ky][kx]     * wv;
                    acc[o][0][1] += xv[ky][kx + 1] * wv;
                    acc[o][1][0] += xv[ky + 1][kx]     * wv;
                    acc[o][1][1] += xv[ky + 1][kx + 1] * wv;
                }
        }
        __syncthreads();
    }
#pragma unroll
    for (int o = 0; o < 8; o++)
#pragma unroll
        for (int r = 0; r < 2; r++)
#pragma unroll
            for (int c2 = 0; c2 < 2; c2++)
                g_y[((b * C + co0 + o) << 12) + ((ty0 + py + r) << 6) + tx0 + px + c2] =
                    acc[o][r][c2];
}

// ---------------- K2: per-channel batch stats ----------------
__global__ void bnstats_kernel(const float* __restrict__ gamma, const float* __restrict__ beta) {
    const int c = blockIdx.x;
    const int t = threadIdx.x;
    float s = 0.f, ss = 0.f;
    for (int i = t; i < B * N; i += 256) {
        int b = i >> 12, n = i & 4095;
        float v = g_y[((b * C + c) << 12) + n];
        s += v; ss += v * v;
    }
    __shared__ float r1[256], r2[256];
    r1[t] = s; r2[t] = ss;
    __syncthreads();
    for (int off = 128; off; off >>= 1) {
        if (t < off) { r1[t] += r1[t + off]; r2[t] += r2[t + off]; }
        __syncthreads();
    }
    if (t == 0) {
        const float inv = 1.f / (float)(B * N);
        float mean = r1[0] * inv;
        float var  = r2[0] * inv - mean * mean;
        float istd = rsqrtf(var + 1e-5f);
        float sc = gamma[c] * istd;
        g_scale[c] = sc;
        g_shift[c] = beta[c] - mean * sc;
    }
}

// ---------------- K3: BN + ReLU, d_out = 3*feat ----------------
__global__ void bnrelu_kernel(float* __restrict__ out) {
    const int total = B * C * N;
    for (int i = blockIdx.x * 256 + threadIdx.x; i < total; i += 2048 * 256) {
        int c = (i >> 12) & (C - 1);
        float v = fmaxf(g_y[i] * g_scale[c] + g_shift[c], 0.f);
        g_y[i] = v;
        out[i] = 3.f * v;
    }
}

// ---------------- K4: fused q/k/v projection ----------
__global__ void qkv_kernel(const float* __restrict__ qw, const float* __restrict__ qb,
                           const float* __restrict__ kw, const float* __restrict__ kb,
                           const float* __restrict__ vw, const float* __restrict__ vb) {
    const int b = blockIdx.y, n0 = blockIdx.x * 64;
    const int t = threadIdx.x;
    __shared__ float Wc[160 * 33];
    __shared__ float fs[32 * 64];
    __shared__ float bias_s[160];
    if (t < 160) bias_s[t] = (t < 16) ? qb[t] : (t < 32 ? kb[t - 16] : vb[t - 32]);
    const int og = t >> 4, nl = (t & 15) * 4;

    float4 acc[10];
#pragma unroll
    for (int j = 0; j < 10; j++) acc[j] = make_float4(0.f, 0.f, 0.f, 0.f);

    for (int cc = 0; cc < C; cc += 32) {
        for (int i = t; i < 160 * 32; i += 256) {
            int o = i >> 5, c = i & 31;
            float wv = (o < 16) ? qw[o * C + cc + c]
                     : (o < 32) ? kw[(o - 16) * C + cc + c]
                                : vw[(o - 32) * C + cc + c];
            Wc[o * 33 + c] = wv;
        }
        for (int i = t; i < 2048; i += 256) {
            int c = i >> 6, n = i & 63;
            fs[c * 64 + n] = g_y[((b * C + cc + c) << 12) + n0 + n];
        }
        __syncthreads();
#pragma unroll
        for (int c = 0; c < 32; c++) {
            float4 fv = *(const float4*)&fs[c * 64 + nl];
#pragma unroll
            for (int j = 0; j < 10; j++) {
                float wv = Wc[(og * 10 + j) * 33 + c];
                acc[j].x += wv * fv.x; acc[j].y += wv * fv.y;
                acc[j].z += wv * fv.z; acc[j].w += wv * fv.w;
            }
        }
        __syncthreads();
    }
#pragma unroll
    for (int j = 0; j < 10; j++) {
        int o = og * 10 + j;
        float bi = bias_s[o];
        acc[j].x += bi; acc[j].y += bi; acc[j].z += bi; acc[j].w += bi;
        float* dst = (o < 16) ? &g_q[(b * CQK + o) << 12]
                   : (o < 32) ? &g_k[(b * CQK + o - 16) << 12]
                              : &g_v[(b * C + o - 32) << 12];
        *(float4*)&dst[n0 + nl] = acc[j];
    }
}

// ---------------- K5: CAM energy ----------------
__global__ void cam_energy_kernel() {
    const int b = blockIdx.y;
    const int c0 = (blockIdx.x >> 2) * 32, d0 = (blockIdx.x & 3) * 32;
    const int t = threadIdx.x;
    const int lc = (t >> 4) * 2, ld = 32 + (t & 15) * 2;
    __shared__ float fs[64 * 33];
    float acc[2][2] = {{0.f, 0.f}, {0.f, 0.f}};

    for (int n0 = 0; n0 < N; n0 += 32) {
        for (int i = t; i < 2048; i += 256) {
            int r = i >> 5, n = i & 31;
            int ch = (r < 32) ? (c0 + r) : (d0 + r - 32);
            fs[r * 33 + n] = g_y[((b * C + ch) << 12) + n0 + n];
        }
        __syncthreads();
#pragma unroll
        for (int n = 0; n < 32; n++) {
            float a0 = fs[lc * 33 + n],       a1 = fs[(lc + 1) * 33 + n];
            float b0 = fs[ld * 33 + n],       b1 = fs[(ld + 1) * 33 + n];
            acc[0][0] += a0 * b0; acc[0][1] += a0 * b1;
            acc[1][0] += a1 * b0; acc[1][1] += a1 * b1;
        }
        __syncthreads();
    }
#pragma unroll
    for (int i = 0; i < 2; i++)
#pragma unroll
        for (int j = 0; j < 2; j++)
            g_e[(b * C + c0 + lc + i) * C + d0 + (ld - 32) + j] = acc[i][j];
}

// ---------------- K6: CAM attn ------------------
__global__ void cam_attn_kernel() {
    const int b = blockIdx.y, c = blockIdx.x, t = threadIdx.x;
    float v = g_e[((b * C + c) << 7) + t];
    __shared__ float red[128];
    red[t] = v;
    __syncthreads();
    for (int off = 64; off; off >>= 1) {
        if (t < off) red[t] = fmaxf(red[t], red[t + off]);
        __syncthreads();
    }
    g_e[((b * C + c) << 7) + t] = tanhf(red[0] - v);
}

// ---------------- K7: CAM out ----------------
__global__ void cam_out_kernel(const float* __restrict__ gca, float* __restrict__ out) {
    const int b = blockIdx.y, n0 = blockIdx.x * 64;
    const int t = threadIdx.x;
    __shared__ float At[128 * 33];
    __shared__ float fs[32 * 64];
    const int og = t >> 4, nl = (t & 15) * 4;

    float4 acc[8];
#pragma unroll
    for (int j = 0; j < 8; j++) acc[j] = make_float4(0.f, 0.f, 0.f, 0.f);

    for (int dc = 0; dc < C; dc += 32) {
        for (int i = t; i < 128 * 32; i += 256) {
            int o = i >> 5, d = i & 31;
            At[o * 33 + d] = g_e[((b * C + o) << 7) + dc + d];
        }
        for (int i = t; i < 2048; i += 256) {
            int d = i >> 6, n = i & 63;
            fs[d * 64 + n] = g_y[((b * C + dc + d) << 12) + n0 + n];
        }
        __syncthreads();
#pragma unroll
        for (int d = 0; d < 32; d++) {
            float4 fv = *(const float4*)&fs[d * 64 + nl];
#pragma unroll
            for (int j = 0; j < 8; j++) {
                float wv = At[(og * 8 + j) * 33 + d];
                acc[j].x += wv * fv.x; acc[j].y += wv * fv.y;
                acc[j].z += wv * fv.z; acc[j].w += wv * fv.w;
            }
        }
        __syncthreads();
    }
    const float g = gca[0];
#pragma unroll
    for (int j = 0; j < 8; j++) {
        int o = og * 8 + j;
        float4* dp = (float4*)&out[((b * C + o) << 12) + n0 + nl];
        float4 cur = *dp;
        cur.x += g * acc[j].x; cur.y += g * acc[j].y;
        cur.z += g * acc[j].z; cur.w += g * acc[j].w;
        *dp = cur;
    }
}

// ---------------- K8: PAM via mma.sync tf32 (flash-style) --------------------
// out[c][m] += gamma * sum_n v[c][n] * tanh(sum_q q[q][m] k[q][n])
// Per CTA: b, m-tile of 64. Loop n chunks of 32:
//   MMA1: E[64m x 32n] = q^T k (K=16, 2 k8 steps); 16 tiles, 2 per warp
//   tanh.approx -> S^T in SMEM (sn[n][m], pitch 72 -> conflict-free B frags)
//   MMA2: O[128c x 64m] += v * S^T (warp = 32c x 32m, 4 k8 steps)
__global__ __launch_bounds__(256)
void pam_mma_kernel(const float* __restrict__ gpa, float* __restrict__ out) {
    __shared__ uint32_t qs[64 * 20];    // q^T  [m][qc]
    __shared__ uint32_t ks_s[16 * 36];  // k    [qc][n]
    __shared__ uint32_t vs[128 * 36];   // v    [c][n]
    __shared__ uint32_t sn[32 * 72];    // S^T  [n][m]

    const int b = blockIdx.y, m0 = blockIdx.x * 64;
    const int t = threadIdx.x;
    const int w = t >> 5, lane = t & 31;
    const int lq = lane >> 2, lr = lane & 3;

    // load q^T once (tf32)
    for (int i = t; i < 1024; i += 256) {
        int qc = i >> 6, m = i & 63;
        qs[m * 20 + qc] = f32_tf32(g_q[((b * CQK + qc) << 12) + m0 + m]);
    }
    __syncthreads();

    // hoist A fragments of q for the E phase (warp handles E-tiles 2w, 2w+1; same mi)
    const int mi_e = w >> 1;
    uint32_t aq[2][4];
#pragma unroll
    for (int ks = 0; ks < 2; ks++) {
        int r = mi_e * 16 + lq, c = ks * 8 + lr;
        aq[ks][0] = qs[r * 20 + c];
        aq[ks][1] = qs[(r + 8) * 20 + c];
        aq[ks][2] = qs[r * 20 + c + 4];
        aq[ks][3] = qs[(r + 8) * 20 + c + 4];
    }

    const int cw = (w & 3) * 32, mw = (w >> 2) * 32;
    float acc[2][4][4];
#pragma unroll
    for (int ct = 0; ct < 2; ct++)
#pragma unroll
        for (int mt = 0; mt < 4; mt++)
#pragma unroll
            for (int i = 0; i < 4; i++) acc[ct][mt][i] = 0.f;

    for (int ch = 0; ch < 128; ch++) {
        const int n0 = ch * 32;
        __syncthreads();   // previous iteration fully done with ks_s/vs/sn
        // load k chunk (tf32)
        {
            int qc = t >> 4, n = (t & 15) * 2;
            float2 kv = *(const float2*)&g_k[((b * CQK + qc) << 12) + n0 + n];
            ks_s[qc * 36 + n]     = f32_tf32(kv.x);
            ks_s[qc * 36 + n + 1] = f32_tf32(kv.y);
        }
        // load v chunk (tf32)
#pragma unroll
        for (int p = 0; p < 4; p++) {
            int i = t + p * 256;
            int c = i >> 3, n4 = (i & 7) * 4;
            float4 vv = *(const float4*)&g_v[((b * C + c) << 12) + n0 + n4];
            uint4 u;
            u.x = f32_tf32(vv.x); u.y = f32_tf32(vv.y);
            u.z = f32_tf32(vv.z); u.w = f32_tf32(vv.w);
            *(uint4*)&vs[c * 36 + n4] = u;
        }
        __syncthreads();

        // E phase: this warp's 2 tiles
        float e[2][4];
#pragma unroll
        for (int j = 0; j < 2; j++) {
#pragma unroll
            for (int i = 0; i < 4; i++) e[j][i] = 0.f;
            int ni = (2 * w + j) & 3;
#pragma unroll
            for (int ks = 0; ks < 2; ks++) {
                uint32_t b0 = ks_s[(ks * 8 + lr) * 36 + ni * 8 + lq];
                uint32_t b1 = ks_s[(ks * 8 + lr + 4) * 36 + ni * 8 + lq];
                mma_tf32(e[j], aq[ks], b0, b1);
            }
        }
        // tanh + store S^T
#pragma unroll
        for (int j = 0; j < 2; j++) {
            int ni = (2 * w + j) & 3;
            int m = mi_e * 16 + lq;
            int n = ni * 8 + lr * 2;
            sn[n * 72 + m]           = f32_tf32(tanh_ap(e[j][0]));
            sn[(n + 1) * 72 + m]     = f32_tf32(tanh_ap(e[j][1]));
            sn[n * 72 + m + 8]       = f32_tf32(tanh_ap(e[j][2]));
            sn[(n + 1) * 72 + m + 8] = f32_tf32(tanh_ap(e[j][3]));
        }
        __syncthreads();

        // GEMM2: acc += v * S^T
#pragma unroll
        for (int ks = 0; ks < 4; ks++) {
            uint32_t a[2][4], bb[4][2];
#pragma unroll
            for (int ct = 0; ct < 2; ct++) {
                int r = cw + ct * 16 + lq, c = ks * 8 + lr;
                a[ct][0] = vs[r * 36 + c];
                a[ct][1] = vs[(r + 8) * 36 + c];
                a[ct][2] = vs[r * 36 + c + 4];
                a[ct][3] = vs[(r + 8) * 36 + c + 4];
            }
#pragma unroll
            for (int mt = 0; mt < 4; mt++) {
                int r = ks * 8 + lr, c = mw + mt * 8 + lq;
                bb[mt][0] = sn[r * 72 + c];
                bb[mt][1] = sn[(r + 4) * 72 + c];
            }
#pragma unroll
            for (int ct = 0; ct < 2; ct++)
#pragma unroll
                for (int mt = 0; mt < 4; mt++)
                    mma_tf32(acc[ct][mt], a[ct], bb[mt][0], bb[mt][1]);
        }
    }

    // epilogue: out += gamma * acc
    const float g = gpa[0];
#pragma unroll
    for (int ct = 0; ct < 2; ct++) {
#pragma unroll
        for (int rr = 0; rr < 2; rr++) {
            int c = cw + ct * 16 + lq + rr * 8;
            float* row = &out[((b * C + c) << 12) + m0 + mw];
#pragma unroll
            for (int mt = 0; mt < 4; mt++) {
                int m = mt * 8 + lr * 2;
                float2* p = (float2*)&row[m];
                float2 cur = *p;
                cur.x += g * acc[ct][mt][rr * 2];
                cur.y += g * acc[ct][mt][rr * 2 + 1];
                *p = cur;
            }
        }
    }
}

// ---------------- launch ----------------
extern "C" void kernel_launch(void* const* d_in, const int* in_sizes, int n_in,
                              void* d_out, int out_size) {
    const float* x       = (const float*)d_in[0];
    const float* conv_w  = (const float*)d_in[1];
    const float* bn_g    = (const float*)d_in[2];
    const float* bn_b    = (const float*)d_in[3];
    const float* q_w     = (const float*)d_in[4];
    const float* q_b     = (const float*)d_in[5];
    const float* k_w     = (const float*)d_in[6];
    const float* k_b     = (const float*)d_in[7];
    const float* v_w     = (const float*)d_in[8];
    const float* v_b     = (const float*)d_in[9];
    const float* gca     = (const float*)d_in[10];
    const float* gpa     = (const float*)d_in[11];
    float* out = (float*)d_out;

    conv_kernel<<<dim3(2, 2, B * 16), 256>>>(x, conv_w);
    bnstats_kernel<<<C, 256>>>(bn_g, bn_b);
    bnrelu_kernel<<<2048, 256>>>(out);
    qkv_kernel<<<dim3(64, B), 256>>>(q_w, q_b, k_w, k_b, v_w, v_b);
    cam_energy_kernel<<<dim3(16, B), 256>>>();
    cam_attn_kernel<<<dim3(C, B), 128>>>();
    cam_out_kernel<<<dim3(64, B), 256>>>(gca, out);
    pam_mma_kernel<<<dim3(64, B), 256>>>(gpa, out);
}

// round 4
// speedup vs baseline: 2.0762x; 1.4495x over previous
#include <cuda_runtime.h>
#include <math.h>
#include <stdint.h>

// Problem constants
#define B   4
#define CIN 256
#define C   128
#define HW  64
#define N   4096          // HW*HW
#define CQK 16

// ---------------- scratch (device globals; no allocation) ----------------
__device__ float g_y[B * C * N];        // conv out, then feat (in-place) : 8 MB
__device__ float g_scale[C];
__device__ float g_shift[C];
__device__ float g_q[B * CQK * N];
__device__ float g_k[B * CQK * N];
__device__ float g_v[B * C * N];        // 8 MB
__device__ float g_e[B * C * C];        // CAM energy -> attn (in place)
__device__ uint32_t g_w2hi[9 * 128 * 256];  // conv weights, tf32 hi, [off][co][ci]
__device__ uint32_t g_w2lo[9 * 128 * 256];  // tf32 residual

// ================= base-ISA tensor helpers (NO tcgen05 — plain sm_103) ======
__device__ __forceinline__ uint32_t f32_tf32(float f) {
    uint32_t r;
    asm("cvt.rna.tf32.f32 %0, %1;" : "=r"(r) : "f"(f));
    return r;
}
__device__ __forceinline__ float tanh_ap(float x) {
    float y;
    asm("tanh.approx.f32 %0, %1;" : "=f"(y) : "f"(x));
    return y;
}
// D += A(16x8 tf32) * B(8x8 tf32), fp32 accum
__device__ __forceinline__ void mma_tf32(float* d, const uint32_t* a, uint32_t b0, uint32_t b1) {
    asm volatile(
        "mma.sync.aligned.m16n8k8.row.col.f32.tf32.tf32.f32 "
        "{%0,%1,%2,%3}, {%4,%5,%6,%7}, {%8,%9}, {%0,%1,%2,%3};"
        : "+f"(d[0]), "+f"(d[1]), "+f"(d[2]), "+f"(d[3])
        : "r"(a[0]), "r"(a[1]), "r"(a[2]), "r"(a[3]), "r"(b0), "r"(b1));
}

// ---------------- K0: weight prep: w -> tf32 hi/lo, [off][co][ci] ------------
__global__ void wprep_kernel(const float* __restrict__ w) {
    int i = blockIdx.x * 256 + threadIdx.x;
    if (i >= 9 * 128 * 256) return;
    int off = i >> 15;
    int rem = i & 32767;
    int co = rem >> 8, ci = rem & 255;
    float v = w[(co * 256 + ci) * 9 + off];
    uint32_t hi = f32_tf32(v);
    g_w2hi[i] = hi;
    g_w2lo[i] = f32_tf32(v - __uint_as_float(hi));
}

// ---------------- K1: 3x3 conv via mma.sync tf32 (3xTF32 split) --------------
// CTA: one image row y (64 px) x 128 out channels; 8 warps = 4(co) x 2(px).
// SMEM (uint32 words):
#define XS_HI 0
#define XS_LO 6400
#define WS_HI 12800
#define WS_LO 17408
#define CONV_SMEM_WORDS 22016

__global__ __launch_bounds__(256)
void conv_tc_kernel(const float* __restrict__ x) {
    extern __shared__ uint32_t cs[];
    const int y = blockIdx.x, b = blockIdx.y;
    const int t = threadIdx.x;
    const int w = t >> 5, lane = t & 31;
    const int lq = lane >> 2, lr = lane & 3;
    const int cw = (w >> 1) * 32;     // co base of this warp
    const int pw = (w & 1) * 32;      // px base of this warp

    float acc[2][4][4];
#pragma unroll
    for (int ct = 0; ct < 2; ct++)
#pragma unroll
        for (int nt = 0; nt < 4; nt++)
#pragma unroll
            for (int i = 0; i < 4; i++) acc[ct][nt][i] = 0.f;

    for (int ci0 = 0; ci0 < CIN; ci0 += 32) {
        __syncthreads();
        // stage x tile with halo: 32 ci x 3 rows x 66 px (xx 0..65 = gx -1..64)
        for (int i = t; i < 32 * 198; i += 256) {
            int ci = i / 198, rem = i % 198;
            int yy = rem / 66, xx = rem % 66;
            int gy = y + yy - 1, gx = xx - 1;
            float v = 0.f;
            if (gy >= 0 && gy < HW && gx >= 0 && gx < HW)
                v = x[(((b * CIN + ci0 + ci) << 6) + gy) * 64 + gx];
            uint32_t hi = f32_tf32(v);
            int a = ci * 200 + yy * 66 + xx;
            cs[XS_HI + a] = hi;
            cs[XS_LO + a] = f32_tf32(v - __uint_as_float(hi));
        }

#pragma unroll 1
        for (int off = 0; off < 9; off++) {
            __syncthreads();
            // stage weights for this offset: [co][ci] pitch 36
            {
                int base = (off << 15) + ci0;
#pragma unroll
                for (int p = 0; p < 16; p++) {
                    int i = t + p * 256;
                    int co = i >> 5, ci = i & 31;
                    int src = base + (co << 8) + ci;
                    cs[WS_HI + co * 36 + ci] = g_w2hi[src];
                    cs[WS_LO + co * 36 + ci] = g_w2lo[src];
                }
            }
            __syncthreads();
            const int ky = off / 3, kx = off % 3;
            const int xbase = ky * 66 + kx + pw;

#pragma unroll
            for (int ks = 0; ks < 4; ks++) {
                int k = ks * 8;
                uint32_t ahi[2][4], alo[2][4];
#pragma unroll
                for (int ct = 0; ct < 2; ct++) {
                    int r = (cw + ct * 16 + lq) * 36 + k + lr;
                    ahi[ct][0] = cs[WS_HI + r];
                    ahi[ct][1] = cs[WS_HI + r + 8 * 36];
                    ahi[ct][2] = cs[WS_HI + r + 4];
                    ahi[ct][3] = cs[WS_HI + r + 8 * 36 + 4];
                    alo[ct][0] = cs[WS_LO + r];
                    alo[ct][1] = cs[WS_LO + r + 8 * 36];
                    alo[ct][2] = cs[WS_LO + r + 4];
                    alo[ct][3] = cs[WS_LO + r + 8 * 36 + 4];
                }
#pragma unroll
                for (int nt = 0; nt < 4; nt++) {
                    int a0 = (k + lr) * 200 + xbase + nt * 8 + lq;
                    int a1 = a0 + 4 * 200;
                    uint32_t bh0 = cs[XS_HI + a0], bh1 = cs[XS_HI + a1];
                    uint32_t bl0 = cs[XS_LO + a0], bl1 = cs[XS_LO + a1];
#pragma unroll
                    for (int ct = 0; ct < 2; ct++) {
                        mma_tf32(acc[ct][nt], ahi[ct], bh0, bh1);
                        mma_tf32(acc[ct][nt], ahi[ct], bl0, bl1);
                        mma_tf32(acc[ct][nt], alo[ct], bh0, bh1);
                    }
                }
            }
        }
    }

    // store to g_y[b][co][y*64+px]
#pragma unroll
    for (int ct = 0; ct < 2; ct++) {
#pragma unroll
        for (int rr = 0; rr < 2; rr++) {
            int co = cw + ct * 16 + lq + rr * 8;
            float* row = &g_y[((b * C + co) << 12) + (y << 6) + pw];
#pragma unroll
            for (int nt = 0; nt < 4; nt++) {
                int m = nt * 8 + lr * 2;
                float2 vv;
                vv.x = acc[ct][nt][rr * 2];
                vv.y = acc[ct][nt][rr * 2 + 1];
                *(float2*)&row[m] = vv;
            }
        }
    }
}

// ---------------- K2: per-channel batch stats ----------------
__global__ void bnstats_kernel(const float* __restrict__ gamma, const float* __restrict__ beta) {
    const int c = blockIdx.x;
    const int t = threadIdx.x;
    float s = 0.f, ss = 0.f;
    for (int i = t; i < B * N; i += 256) {
        int b = i >> 12, n = i & 4095;
        float v = g_y[((b * C + c) << 12) + n];
        s += v; ss += v * v;
    }
    __shared__ float r1[256], r2[256];
    r1[t] = s; r2[t] = ss;
    __syncthreads();
    for (int off = 128; off; off >>= 1) {
        if (t < off) { r1[t] += r1[t + off]; r2[t] += r2[t + off]; }
        __syncthreads();
    }
    if (t == 0) {
        const float inv = 1.f / (float)(B * N);
        float mean = r1[0] * inv;
        float var  = r2[0] * inv - mean * mean;
        float istd = rsqrtf(var + 1e-5f);
        float sc = gamma[c] * istd;
        g_scale[c] = sc;
        g_shift[c] = beta[c] - mean * sc;
    }
}

// ---------------- K3: BN + ReLU, d_out = 3*feat ----------------
__global__ void bnrelu_kernel(float* __restrict__ out) {
    const int total = B * C * N;
    for (int i = blockIdx.x * 256 + threadIdx.x; i < total; i += 2048 * 256) {
        int c = (i >> 12) & (C - 1);
        float v = fmaxf(g_y[i] * g_scale[c] + g_shift[c], 0.f);
        g_y[i] = v;
        out[i] = 3.f * v;
    }
}

// ---------------- K4: fused q/k/v projection ----------
__global__ void qkv_kernel(const float* __restrict__ qw, const float* __restrict__ qb,
                           const float* __restrict__ kw, const float* __restrict__ kb,
                           const float* __restrict__ vw, const float* __restrict__ vb) {
    const int b = blockIdx.y, n0 = blockIdx.x * 64;
    const int t = threadIdx.x;
    __shared__ float Wc[160 * 33];
    __shared__ float fs[32 * 64];
    __shared__ float bias_s[160];
    if (t < 160) bias_s[t] = (t < 16) ? qb[t] : (t < 32 ? kb[t - 16] : vb[t - 32]);
    const int og = t >> 4, nl = (t & 15) * 4;

    float4 acc[10];
#pragma unroll
    for (int j = 0; j < 10; j++) acc[j] = make_float4(0.f, 0.f, 0.f, 0.f);

    for (int cc = 0; cc < C; cc += 32) {
        for (int i = t; i < 160 * 32; i += 256) {
            int o = i >> 5, c = i & 31;
            float wv = (o < 16) ? qw[o * C + cc + c]
                     : (o < 32) ? kw[(o - 16) * C + cc + c]
                                : vw[(o - 32) * C + cc + c];
            Wc[o * 33 + c] = wv;
        }
        for (int i = t; i < 2048; i += 256) {
            int c = i >> 6, n = i & 63;
            fs[c * 64 + n] = g_y[((b * C + cc + c) << 12) + n0 + n];
        }
        __syncthreads();
#pragma unroll
        for (int c = 0; c < 32; c++) {
            float4 fv = *(const float4*)&fs[c * 64 + nl];
#pragma unroll
            for (int j = 0; j < 10; j++) {
                float wv = Wc[(og * 10 + j) * 33 + c];
                acc[j].x += wv * fv.x; acc[j].y += wv * fv.y;
                acc[j].z += wv * fv.z; acc[j].w += wv * fv.w;
            }
        }
        __syncthreads();
    }
#pragma unroll
    for (int j = 0; j < 10; j++) {
        int o = og * 10 + j;
        float bi = bias_s[o];
        acc[j].x += bi; acc[j].y += bi; acc[j].z += bi; acc[j].w += bi;
        float* dst = (o < 16) ? &g_q[(b * CQK + o) << 12]
                   : (o < 32) ? &g_k[(b * CQK + o - 16) << 12]
                              : &g_v[(b * C + o - 32) << 12];
        *(float4*)&dst[n0 + nl] = acc[j];
    }
}

// ---------------- K5: CAM energy ----------------
__global__ void cam_energy_kernel() {
    const int b = blockIdx.y;
    const int c0 = (blockIdx.x >> 2) * 32, d0 = (blockIdx.x & 3) * 32;
    const int t = threadIdx.x;
    const int lc = (t >> 4) * 2, ld = 32 + (t & 15) * 2;
    __shared__ float fs[64 * 33];
    float acc[2][2] = {{0.f, 0.f}, {0.f, 0.f}};

    for (int n0 = 0; n0 < N; n0 += 32) {
        for (int i = t; i < 2048; i += 256) {
            int r = i >> 5, n = i & 31;
            int ch = (r < 32) ? (c0 + r) : (d0 + r - 32);
            fs[r * 33 + n] = g_y[((b * C + ch) << 12) + n0 + n];
        }
        __syncthreads();
#pragma unroll
        for (int n = 0; n < 32; n++) {
            float a0 = fs[lc * 33 + n],       a1 = fs[(lc + 1) * 33 + n];
            float b0 = fs[ld * 33 + n],       b1 = fs[(ld + 1) * 33 + n];
            acc[0][0] += a0 * b0; acc[0][1] += a0 * b1;
            acc[1][0] += a1 * b0; acc[1][1] += a1 * b1;
        }
        __syncthreads();
    }
#pragma unroll
    for (int i = 0; i < 2; i++)
#pragma unroll
        for (int j = 0; j < 2; j++)
            g_e[(b * C + c0 + lc + i) * C + d0 + (ld - 32) + j] = acc[i][j];
}

// ---------------- K6: CAM attn ------------------
__global__ void cam_attn_kernel() {
    const int b = blockIdx.y, c = blockIdx.x, t = threadIdx.x;
    float v = g_e[((b * C + c) << 7) + t];
    __shared__ float red[128];
    red[t] = v;
    __syncthreads();
    for (int off = 64; off; off >>= 1) {
        if (t < off) red[t] = fmaxf(red[t], red[t + off]);
        __syncthreads();
    }
    g_e[((b * C + c) << 7) + t] = tanhf(red[0] - v);
}

// ---------------- K7: CAM out ----------------
__global__ void cam_out_kernel(const float* __restrict__ gca, float* __restrict__ out) {
    const int b = blockIdx.y, n0 = blockIdx.x * 64;
    const int t = threadIdx.x;
    __shared__ float At[128 * 33];
    __shared__ float fs[32 * 64];
    const int og = t >> 4, nl = (t & 15) * 4;

    float4 acc[8];
#pragma unroll
    for (int j = 0; j < 8; j++) acc[j] = make_float4(0.f, 0.f, 0.f, 0.f);

    for (int dc = 0; dc < C; dc += 32) {
        for (int i = t; i < 128 * 32; i += 256) {
            int o = i >> 5, d = i & 31;
            At[o * 33 + d] = g_e[((b * C + o) << 7) + dc + d];
        }
        for (int i = t; i < 2048; i += 256) {
            int d = i >> 6, n = i & 63;
            fs[d * 64 + n] = g_y[((b * C + dc + d) << 12) + n0 + n];
        }
        __syncthreads();
#pragma unroll
        for (int d = 0; d < 32; d++) {
            float4 fv = *(const float4*)&fs[d * 64 + nl];
#pragma unroll
            for (int j = 0; j < 8; j++) {
                float wv = At[(og * 8 + j) * 33 + d];
                acc[j].x += wv * fv.x; acc[j].y += wv * fv.y;
                acc[j].z += wv * fv.z; acc[j].w += wv * fv.w;
            }
        }
        __syncthreads();
    }
    const float g = gca[0];
#pragma unroll
    for (int j = 0; j < 8; j++) {
        int o = og * 8 + j;
        float4* dp = (float4*)&out[((b * C + o) << 12) + n0 + nl];
        float4 cur = *dp;
        cur.x += g * acc[j].x; cur.y += g * acc[j].y;
        cur.z += g * acc[j].z; cur.w += g * acc[j].w;
        *dp = cur;
    }
}

// ---------------- K8: PAM via mma.sync tf32 (flash-style) --------------------
__global__ __launch_bounds__(256)
void pam_mma_kernel(const float* __restrict__ gpa, float* __restrict__ out) {
    __shared__ uint32_t qs[64 * 20];    // q^T  [m][qc]
    __shared__ uint32_t ks_s[16 * 36];  // k    [qc][n]
    __shared__ uint32_t vs[128 * 36];   // v    [c][n]
    __shared__ uint32_t sn[32 * 72];    // S^T  [n][m]

    const int b = blockIdx.y, m0 = blockIdx.x * 64;
    const int t = threadIdx.x;
    const int w = t >> 5, lane = t & 31;
    const int lq = lane >> 2, lr = lane & 3;

    for (int i = t; i < 1024; i += 256) {
        int qc = i >> 6, m = i & 63;
        qs[m * 20 + qc] = f32_tf32(g_q[((b * CQK + qc) << 12) + m0 + m]);
    }
    __syncthreads();

    const int mi_e = w >> 1;
    uint32_t aq[2][4];
#pragma unroll
    for (int ks = 0; ks < 2; ks++) {
        int r = mi_e * 16 + lq, c = ks * 8 + lr;
        aq[ks][0] = qs[r * 20 + c];
        aq[ks][1] = qs[(r + 8) * 20 + c];
        aq[ks][2] = qs[r * 20 + c + 4];
        aq[ks][3] = qs[(r + 8) * 20 + c + 4];
    }

    const int cw = (w & 3) * 32, mw = (w >> 2) * 32;
    float acc[2][4][4];
#pragma unroll
    for (int ct = 0; ct < 2; ct++)
#pragma unroll
        for (int mt = 0; mt < 4; mt++)
#pragma unroll
            for (int i = 0; i < 4; i++) acc[ct][mt][i] = 0.f;

    for (int ch = 0; ch < 128; ch++) {
        const int n0 = ch * 32;
        __syncthreads();
        {
            int qc = t >> 4, n = (t & 15) * 2;
            float2 kv = *(const float2*)&g_k[((b * CQK + qc) << 12) + n0 + n];
            ks_s[qc * 36 + n]     = f32_tf32(kv.x);
            ks_s[qc * 36 + n + 1] = f32_tf32(kv.y);
        }
#pragma unroll
        for (int p = 0; p < 4; p++) {
            int i = t + p * 256;
            int c = i >> 3, n4 = (i & 7) * 4;
            float4 vv = *(const float4*)&g_v[((b * C + c) << 12) + n0 + n4];
            uint4 u;
            u.x = f32_tf32(vv.x); u.y = f32_tf32(vv.y);
            u.z = f32_tf32(vv.z); u.w = f32_tf32(vv.w);
            *(uint4*)&vs[c * 36 + n4] = u;
        }
        __syncthreads();

        float e[2][4];
#pragma unroll
        for (int j = 0; j < 2; j++) {
#pragma unroll
            for (int i = 0; i < 4; i++) e[j][i] = 0.f;
            int ni = (2 * w + j) & 3;
#pragma unroll
            for (int ks = 0; ks < 2; ks++) {
                uint32_t b0 = ks_s[(ks * 8 + lr) * 36 + ni * 8 + lq];
                uint32_t b1 = ks_s[(ks * 8 + lr + 4) * 36 + ni * 8 + lq];
                mma_tf32(e[j], aq[ks], b0, b1);
            }
        }
#pragma unroll
        for (int j = 0; j < 2; j++) {
            int ni = (2 * w + j) & 3;
            int m = mi_e * 16 + lq;
            int n = ni * 8 + lr * 2;
            sn[n * 72 + m]           = f32_tf32(tanh_ap(e[j][0]));
            sn[(n + 1) * 72 + m]     = f32_tf32(tanh_ap(e[j][1]));
            sn[n * 72 + m + 8]       = f32_tf32(tanh_ap(e[j][2]));
            sn[(n + 1) * 72 + m + 8] = f32_tf32(tanh_ap(e[j][3]));
        }
        __syncthreads();

#pragma unroll
        for (int ks = 0; ks < 4; ks++) {
            uint32_t a[2][4], bb[4][2];
#pragma unroll
            for (int ct = 0; ct < 2; ct++) {
                int r = cw + ct * 16 + lq, c = ks * 8 + lr;
                a[ct][0] = vs[r * 36 + c];
                a[ct][1] = vs[(r + 8) * 36 + c];
                a[ct][2] = vs[r * 36 + c + 4];
                a[ct][3] = vs[(r + 8) * 36 + c + 4];
            }
#pragma unroll
            for (int mt = 0; mt < 4; mt++) {
                int r = ks * 8 + lr, c = mw + mt * 8 + lq;
                bb[mt][0] = sn[r * 72 + c];
                bb[mt][1] = sn[(r + 4) * 72 + c];
            }
#pragma unroll
            for (int ct = 0; ct < 2; ct++)
#pragma unroll
                for (int mt = 0; mt < 4; mt++)
                    mma_tf32(acc[ct][mt], a[ct], bb[mt][0], bb[mt][1]);
        }
    }

    const float g = gpa[0];
#pragma unroll
    for (int ct = 0; ct < 2; ct++) {
#pragma unroll
        for (int rr = 0; rr < 2; rr++) {
            int c = cw + ct * 16 + lq + rr * 8;
            float* row = &out[((b * C + c) << 12) + m0 + mw];
#pragma unroll
            for (int mt = 0; mt < 4; mt++) {
                int m = mt * 8 + lr * 2;
                float2* p = (float2*)&row[m];
                float2 cur = *p;
                cur.x += g * acc[ct][mt][rr * 2];
                cur.y += g * acc[ct][mt][rr * 2 + 1];
                *p = cur;
            }
        }
    }
}

// ---------------- launch ----------------
extern "C" void kernel_launch(void* const* d_in, const int* in_sizes, int n_in,
                              void* d_out, int out_size) {
    const float* x       = (const float*)d_in[0];
    const float* conv_w  = (const float*)d_in[1];
    const float* bn_g    = (const float*)d_in[2];
    const float* bn_b    = (const float*)d_in[3];
    const float* q_w     = (const float*)d_in[4];
    const float* q_b     = (const float*)d_in[5];
    const float* k_w     = (const float*)d_in[6];
    const float* k_b     = (const float*)d_in[7];
    const float* v_w     = (const float*)d_in[8];
    const float* v_b     = (const float*)d_in[9];
    const float* gca     = (const float*)d_in[10];
    const float* gpa     = (const float*)d_in[11];
    float* out = (float*)d_out;

    cudaFuncSetAttribute(conv_tc_kernel, cudaFuncAttributeMaxDynamicSharedMemorySize,
                         CONV_SMEM_WORDS * 4);

    wprep_kernel<<<1152, 256>>>(conv_w);
    conv_tc_kernel<<<dim3(64, B), 256, CONV_SMEM_WORDS * 4>>>(x);
    bnstats_kernel<<<C, 256>>>(bn_g, bn_b);
    bnrelu_kernel<<<2048, 256>>>(out);
    qkv_kernel<<<dim3(64, B), 256>>>(q_w, q_b, k_w, k_b, v_w, v_b);
    cam_energy_kernel<<<dim3(16, B), 256>>>();
    cam_attn_kernel<<<dim3(C, B), 128>>>();
    cam_out_kernel<<<dim3(64, B), 256>>>(gca, out);
    pam_mma_kernel<<<dim3(64, B), 256>>>(gpa, out);
}

// round 6
// speedup vs baseline: 2.4132x; 1.1623x over previous
#include <cuda_runtime.h>
#include <math.h>
#include <stdint.h>

// Problem constants
#define B   4
#define CIN 256
#define C   128
#define HW  64
#define N   4096          // HW*HW
#define CQK 16

// ---------------- scratch (device globals; no allocation) ----------------
__device__ float g_y[B * C * N];        // conv out, then feat (in-place) : 8 MB
__device__ float g_scale[C];
__device__ float g_shift[C];
__device__ uint32_t g_q[B * CQK * N];   // tf32 bits
__device__ uint32_t g_k[B * CQK * N];   // tf32 bits
__device__ uint32_t g_v[B * C * N];     // tf32 bits : 8 MB
__device__ float g_e[B * C * C];        // CAM energy -> attn (in place)
__device__ uint32_t g_w2hi[9 * 128 * 256];  // conv weights, tf32 hi, [off][co][ci]
__device__ uint32_t g_w2lo[9 * 128 * 256];  // tf32 residual

// ================= base-ISA tensor helpers (NO tcgen05 — plain sm_103) ======
__device__ __forceinline__ uint32_t f32_tf32(float f) {
    uint32_t r;
    asm("cvt.rna.tf32.f32 %0, %1;" : "=r"(r) : "f"(f));
    return r;
}
__device__ __forceinline__ float tanh_ap(float x) {
    float y;
    asm("tanh.approx.f32 %0, %1;" : "=f"(y) : "f"(x));
    return y;
}
// D += A(16x8 tf32) * B(8x8 tf32), fp32 accum
__device__ __forceinline__ void mma_tf32(float* d, const uint32_t* a, uint32_t b0, uint32_t b1) {
    asm volatile(
        "mma.sync.aligned.m16n8k8.row.col.f32.tf32.tf32.f32 "
        "{%0,%1,%2,%3}, {%4,%5,%6,%7}, {%8,%9}, {%0,%1,%2,%3};"
        : "+f"(d[0]), "+f"(d[1]), "+f"(d[2]), "+f"(d[3])
        : "r"(a[0]), "r"(a[1]), "r"(a[2]), "r"(a[3]), "r"(b0), "r"(b1));
}
__device__ __forceinline__ void cp16(uint32_t saddr, const void* g) {
    asm volatile("cp.async.cg.shared.global [%0], [%1], 16;" :: "r"(saddr), "l"(g));
}
__device__ __forceinline__ void cp_commit() {
    asm volatile("cp.async.commit_group;" ::: "memory");
}
template <int NN> __device__ __forceinline__ void cp_wait() {
    asm volatile("cp.async.wait_group %0;" :: "n"(NN) : "memory");
}

// ---------------- K0: weight prep: w -> tf32 hi/lo, [off][co][ci] ------------
__global__ void wprep_kernel(const float* __restrict__ w) {
    int i = blockIdx.x * 256 + threadIdx.x;
    if (i >= 9 * 128 * 256) return;
    int off = i >> 15;
    int rem = i & 32767;
    int co = rem >> 8, ci = rem & 255;
    float v = w[(co * 256 + ci) * 9 + off];
    uint32_t hi = f32_tf32(v);
    g_w2hi[i] = hi;
    g_w2lo[i] = f32_tf32(v - __uint_as_float(hi));
}

// ---------------- K1: 3x3 conv via mma.sync tf32 (3xTF32 split) --------------
#define XS_HI 0
#define XS_LO 6400
#define WS_HI 12800
#define WS_LO 17408
#define CONV_SMEM_WORDS 22016

__global__ __launch_bounds__(256)
void conv_tc_kernel(const float* __restrict__ x) {
    extern __shared__ uint32_t cs[];
    const int y = blockIdx.x, b = blockIdx.y;
    const int t = threadIdx.x;
    const int w = t >> 5, lane = t & 31;
    const int lq = lane >> 2, lr = lane & 3;
    const int cw = (w >> 1) * 32;
    const int pw = (w & 1) * 32;

    float acc[2][4][4];
#pragma unroll
    for (int ct = 0; ct < 2; ct++)
#pragma unroll
        for (int nt = 0; nt < 4; nt++)
#pragma unroll
            for (int i = 0; i < 4; i++) acc[ct][nt][i] = 0.f;

    for (int ci0 = 0; ci0 < CIN; ci0 += 32) {
        __syncthreads();
        for (int i = t; i < 32 * 198; i += 256) {
            int ci = i / 198, rem = i % 198;
            int yy = rem / 66, xx = rem % 66;
            int gy = y + yy - 1, gx = xx - 1;
            float v = 0.f;
            if (gy >= 0 && gy < HW && gx >= 0 && gx < HW)
                v = x[(((b * CIN + ci0 + ci) << 6) + gy) * 64 + gx];
            uint32_t hi = f32_tf32(v);
            int a = ci * 200 + yy * 66 + xx;
            cs[XS_HI + a] = hi;
            cs[XS_LO + a] = f32_tf32(v - __uint_as_float(hi));
        }

#pragma unroll 1
        for (int off = 0; off < 9; off++) {
            __syncthreads();
            {
                int base = (off << 15) + ci0;
#pragma unroll
                for (int p = 0; p < 16; p++) {
                    int i = t + p * 256;
                    int co = i >> 5, ci = i & 31;
                    int src = base + (co << 8) + ci;
                    cs[WS_HI + co * 36 + ci] = g_w2hi[src];
                    cs[WS_LO + co * 36 + ci] = g_w2lo[src];
                }
            }
            __syncthreads();
            const int ky = off / 3, kx = off % 3;
            const int xbase = ky * 66 + kx + pw;

#pragma unroll
            for (int ks = 0; ks < 4; ks++) {
                int k = ks * 8;
                uint32_t ahi[2][4], alo[2][4];
#pragma unroll
                for (int ct = 0; ct < 2; ct++) {
                    int r = (cw + ct * 16 + lq) * 36 + k + lr;
                    ahi[ct][0] = cs[WS_HI + r];
                    ahi[ct][1] = cs[WS_HI + r + 8 * 36];
                    ahi[ct][2] = cs[WS_HI + r + 4];
                    ahi[ct][3] = cs[WS_HI + r + 8 * 36 + 4];
                    alo[ct][0] = cs[WS_LO + r];
                    alo[ct][1] = cs[WS_LO + r + 8 * 36];
                    alo[ct][2] = cs[WS_LO + r + 4];
                    alo[ct][3] = cs[WS_LO + r + 8 * 36 + 4];
                }
#pragma unroll
                for (int nt = 0; nt < 4; nt++) {
                    int a0 = (k + lr) * 200 + xbase + nt * 8 + lq;
                    int a1 = a0 + 4 * 200;
                    uint32_t bh0 = cs[XS_HI + a0], bh1 = cs[XS_HI + a1];
                    uint32_t bl0 = cs[XS_LO + a0], bl1 = cs[XS_LO + a1];
#pragma unroll
                    for (int ct = 0; ct < 2; ct++) {
                        mma_tf32(acc[ct][nt], ahi[ct], bh0, bh1);
                        mma_tf32(acc[ct][nt], ahi[ct], bl0, bl1);
                        mma_tf32(acc[ct][nt], alo[ct], bh0, bh1);
                    }
                }
            }
        }
    }

#pragma unroll
    for (int ct = 0; ct < 2; ct++) {
#pragma unroll
        for (int rr = 0; rr < 2; rr++) {
            int co = cw + ct * 16 + lq + rr * 8;
            float* row = &g_y[((b * C + co) << 12) + (y << 6) + pw];
#pragma unroll
            for (int nt = 0; nt < 4; nt++) {
                int m = nt * 8 + lr * 2;
                float2 vv;
                vv.x = acc[ct][nt][rr * 2];
                vv.y = acc[ct][nt][rr * 2 + 1];
                *(float2*)&row[m] = vv;
            }
        }
    }
}

// ---------------- K2: per-channel batch stats ----------------
__global__ void bnstats_kernel(const float* __restrict__ gamma, const float* __restrict__ beta) {
    const int c = blockIdx.x;
    const int t = threadIdx.x;
    float s = 0.f, ss = 0.f;
    for (int i = t; i < B * N; i += 256) {
        int b = i >> 12, n = i & 4095;
        float v = g_y[((b * C + c) << 12) + n];
        s += v; ss += v * v;
    }
    __shared__ float r1[256], r2[256];
    r1[t] = s; r2[t] = ss;
    __syncthreads();
    for (int off = 128; off; off >>= 1) {
        if (t < off) { r1[t] += r1[t + off]; r2[t] += r2[t + off]; }
        __syncthreads();
    }
    if (t == 0) {
        const float inv = 1.f / (float)(B * N);
        float mean = r1[0] * inv;
        float var  = r2[0] * inv - mean * mean;
        float istd = rsqrtf(var + 1e-5f);
        float sc = gamma[c] * istd;
        g_scale[c] = sc;
        g_shift[c] = beta[c] - mean * sc;
    }
}

// ---------------- K3: BN + ReLU, d_out = 3*feat ----------------
__global__ void bnrelu_kernel(float* __restrict__ out) {
    const int total = B * C * N;
    for (int i = blockIdx.x * 256 + threadIdx.x; i < total; i += 2048 * 256) {
        int c = (i >> 12) & (C - 1);
        float v = fmaxf(g_y[i] * g_scale[c] + g_shift[c], 0.f);
        g_y[i] = v;
        out[i] = 3.f * v;
    }
}

// ---------------- K4: fused q/k/v projection (writes tf32 bits) --------------
__global__ void qkv_kernel(const float* __restrict__ qw, const float* __restrict__ qb,
                           const float* __restrict__ kw, const float* __restrict__ kb,
                           const float* __restrict__ vw, const float* __restrict__ vb) {
    const int b = blockIdx.y, n0 = blockIdx.x * 64;
    const int t = threadIdx.x;
    __shared__ float Wc[160 * 33];
    __shared__ float fs[32 * 64];
    __shared__ float bias_s[160];
    if (t < 160) bias_s[t] = (t < 16) ? qb[t] : (t < 32 ? kb[t - 16] : vb[t - 32]);
    const int og = t >> 4, nl = (t & 15) * 4;

    float4 acc[10];
#pragma unroll
    for (int j = 0; j < 10; j++) acc[j] = make_float4(0.f, 0.f, 0.f, 0.f);

    for (int cc = 0; cc < C; cc += 32) {
        for (int i = t; i < 160 * 32; i += 256) {
            int o = i >> 5, c = i & 31;
            float wv = (o < 16) ? qw[o * C + cc + c]
                     : (o < 32) ? kw[(o - 16) * C + cc + c]
                                : vw[(o - 32) * C + cc + c];
            Wc[o * 33 + c] = wv;
        }
        for (int i = t; i < 2048; i += 256) {
            int c = i >> 6, n = i & 63;
            fs[c * 64 + n] = g_y[((b * C + cc + c) << 12) + n0 + n];
        }
        __syncthreads();
#pragma unroll
        for (int c = 0; c < 32; c++) {
            float4 fv = *(const float4*)&fs[c * 64 + nl];
#pragma unroll
            for (int j = 0; j < 10; j++) {
                float wv = Wc[(og * 10 + j) * 33 + c];
                acc[j].x += wv * fv.x; acc[j].y += wv * fv.y;
                acc[j].z += wv * fv.z; acc[j].w += wv * fv.w;
            }
        }
        __syncthreads();
    }
#pragma unroll
    for (int j = 0; j < 10; j++) {
        int o = og * 10 + j;
        float bi = bias_s[o];
        uint4 u;
        u.x = f32_tf32(acc[j].x + bi);
        u.y = f32_tf32(acc[j].y + bi);
        u.z = f32_tf32(acc[j].z + bi);
        u.w = f32_tf32(acc[j].w + bi);
        uint32_t* dst = (o < 16) ? &g_q[(b * CQK + o) << 12]
                      : (o < 32) ? &g_k[(b * CQK + o - 16) << 12]
                                 : &g_v[(b * C + o - 32) << 12];
        *(uint4*)&dst[n0 + nl] = u;
    }
}

// ---------------- K5: CAM energy ----------------
__global__ void cam_energy_kernel() {
    const int b = blockIdx.y;
    const int c0 = (blockIdx.x >> 2) * 32, d0 = (blockIdx.x & 3) * 32;
    const int t = threadIdx.x;
    const int lc = (t >> 4) * 2, ld = 32 + (t & 15) * 2;
    __shared__ float fs[64 * 33];
    float acc[2][2] = {{0.f, 0.f}, {0.f, 0.f}};

    for (int n0 = 0; n0 < N; n0 += 32) {
        for (int i = t; i < 2048; i += 256) {
            int r = i >> 5, n = i & 31;
            int ch = (r < 32) ? (c0 + r) : (d0 + r - 32);
            fs[r * 33 + n] = g_y[((b * C + ch) << 12) + n0 + n];
        }
        __syncthreads();
#pragma unroll
        for (int n = 0; n < 32; n++) {
            float a0 = fs[lc * 33 + n],       a1 = fs[(lc + 1) * 33 + n];
            float b0 = fs[ld * 33 + n],       b1 = fs[(ld + 1) * 33 + n];
            acc[0][0] += a0 * b0; acc[0][1] += a0 * b1;
            acc[1][0] += a1 * b0; acc[1][1] += a1 * b1;
        }
        __syncthreads();
    }
#pragma unroll
    for (int i = 0; i < 2; i++)
#pragma unroll
        for (int j = 0; j < 2; j++)
            g_e[(b * C + c0 + lc + i) * C + d0 + (ld - 32) + j] = acc[i][j];
}

// ---------------- K6: CAM attn ------------------
__global__ void cam_attn_kernel() {
    const int b = blockIdx.y, c = blockIdx.x, t = threadIdx.x;
    float v = g_e[((b * C + c) << 7) + t];
    __shared__ float red[128];
    red[t] = v;
    __syncthreads();
    for (int off = 64; off; off >>= 1) {
        if (t < off) red[t] = fmaxf(red[t], red[t + off]);
        __syncthreads();
    }
    g_e[((b * C + c) << 7) + t] = tanhf(red[0] - v);
}

// ---------------- K7: CAM out ----------------
__global__ void cam_out_kernel(const float* __restrict__ gca, float* __restrict__ out) {
    const int b = blockIdx.y, n0 = blockIdx.x * 64;
    const int t = threadIdx.x;
    __shared__ float At[128 * 33];
    __shared__ float fs[32 * 64];
    const int og = t >> 4, nl = (t & 15) * 4;

    float4 acc[8];
#pragma unroll
    for (int j = 0; j < 8; j++) acc[j] = make_float4(0.f, 0.f, 0.f, 0.f);

    for (int dc = 0; dc < C; dc += 32) {
        for (int i = t; i < 128 * 32; i += 256) {
            int o = i >> 5, d = i & 31;
            At[o * 33 + d] = g_e[((b * C + o) << 7) + dc + d];
        }
        for (int i = t; i < 2048; i += 256) {
            int d = i >> 6, n = i & 63;
            fs[d * 64 + n] = g_y[((b * C + dc + d) << 12) + n0 + n];
        }
        __syncthreads();
#pragma unroll
        for (int d = 0; d < 32; d++) {
            float4 fv = *(const float4*)&fs[d * 64 + nl];
#pragma unroll
            for (int j = 0; j < 8; j++) {
                float wv = At[(og * 8 + j) * 33 + d];
                acc[j].x += wv * fv.x; acc[j].y += wv * fv.y;
                acc[j].z += wv * fv.z; acc[j].w += wv * fv.w;
            }
        }
        __syncthreads();
    }
    const float g = gca[0];
#pragma unroll
    for (int j = 0; j < 8; j++) {
        int o = og * 8 + j;
        float4* dp = (float4*)&out[((b * C + o) << 12) + n0 + nl];
        float4 cur = *dp;
        cur.x += g * acc[j].x; cur.y += g * acc[j].y;
        cur.z += g * acc[j].z; cur.w += g * acc[j].w;
        *dp = cur;
    }
}

// ---------------- K8: PAM v2: m-tile 128, n-chunk 64, cp.async dbuf ----------
#define P_QS 0                       // q^T [m][qc] 128x20
#define P_KS 2560                    // k [qc][n]  2 x 16x68
#define P_VS 4736                    // v [c][n]   2 x 128x68
#define P_SN 22144                   // S^T [n][m] 64x136
#define P_WORDS 30848

__global__ __launch_bounds__(256, 1)
void pam_mma_kernel(const float* __restrict__ gpa, float* __restrict__ out) {
    extern __shared__ uint32_t ps[];
    const int b = blockIdx.y, m0 = blockIdx.x * 128;
    const int t = threadIdx.x;
    const int w = t >> 5, lane = t & 31;
    const int lq = lane >> 2, lr = lane & 3;
    const uint32_t sbase = (uint32_t)__cvta_generic_to_shared(ps);

    // load q^T once (already tf32 bits)
    for (int i = t; i < 2048; i += 256) {
        int qc = i >> 7, m = i & 127;
        ps[P_QS + m * 20 + qc] = g_q[((b * CQK + qc) << 12) + m0 + m];
    }

    // staging indices for cp.async
    const int krow = t >> 4, kc4 = (t & 15) * 4;          // 256 thr -> 16x64 k tile
    const uint32_t kdst = sbase + (P_KS + krow * 68 + kc4) * 4;
    const uint32_t* kgsrc = &g_k[((b * CQK + krow) << 12) + kc4];
    const int vrow = t >> 4;                               // + p*16 rows per pass
    const uint32_t vdst = sbase + (P_VS + vrow * 68 + kc4) * 4;
    const uint32_t* vgsrc = &g_v[((b * C + vrow) << 12) + kc4];

    // prologue: stage chunk 0 into buf 0
    cp16(kdst, kgsrc);
#pragma unroll
    for (int p = 0; p < 8; p++)
        cp16(vdst + p * 16 * 68 * 4, vgsrc + (p << 16));
    cp_commit();

    __syncthreads();   // q^T staging visible to ALL warps before fragment hoist

    // hoist q A-fragments (E phase: mi = w)
    uint32_t aq[2][4];
#pragma unroll
    for (int ks = 0; ks < 2; ks++) {
        int r = w * 16 + lq, c = ks * 8 + lr;
        aq[ks][0] = ps[P_QS + r * 20 + c];
        aq[ks][1] = ps[P_QS + (r + 8) * 20 + c];
        aq[ks][2] = ps[P_QS + r * 20 + c + 4];
        aq[ks][3] = ps[P_QS + (r + 8) * 20 + c + 4];
    }

    const int cw = (w & 3) * 32, mw = (w >> 2) * 64;
    float acc[2][8][4];
#pragma unroll
    for (int ct = 0; ct < 2; ct++)
#pragma unroll
        for (int mt = 0; mt < 8; mt++)
#pragma unroll
            for (int i = 0; i < 4; i++) acc[ct][mt][i] = 0.f;

#pragma unroll 1
    for (int ch = 0; ch < 64; ch++) {
        const int pb = ch & 1;
        const uint32_t* ksb = ps + P_KS + pb * (16 * 68);
        const uint32_t* vsb = ps + P_VS + pb * (128 * 68);

        __syncthreads();   // everyone done with buffers being overwritten next
        if (ch + 1 < 64) {
            const int n1 = (ch + 1) * 64;
            const int pn = pb ^ 1;
            cp16(kdst + pn * (16 * 68) * 4, kgsrc + n1);
#pragma unroll
            for (int p = 0; p < 8; p++)
                cp16(vdst + (pn * (128 * 68) + p * 16 * 68) * 4,
                     vgsrc + (p << 16) + n1);
            cp_commit();
            cp_wait<1>();   // chunk ch landed
        } else {
            cp_wait<0>();
        }
        __syncthreads();   // buf pb visible to all

        // E phase: this warp = rows [16w,16w+16) x 64 n
        float e[8][4];
#pragma unroll
        for (int ni = 0; ni < 8; ni++) {
#pragma unroll
            for (int i = 0; i < 4; i++) e[ni][i] = 0.f;
#pragma unroll
            for (int ks = 0; ks < 2; ks++) {
                uint32_t b0 = ksb[(ks * 8 + lr) * 68 + ni * 8 + lq];
                uint32_t b1 = ksb[(ks * 8 + lr + 4) * 68 + ni * 8 + lq];
                mma_tf32(e[ni], aq[ks], b0, b1);
            }
        }
        // tanh -> S^T (tf32 bits)
        {
            int m = w * 16 + lq;
#pragma unroll
            for (int ni = 0; ni < 8; ni++) {
                int n = ni * 8 + lr * 2;
                ps[P_SN + n * 136 + m]           = f32_tf32(tanh_ap(e[ni][0]));
                ps[P_SN + (n + 1) * 136 + m]     = f32_tf32(tanh_ap(e[ni][1]));
                ps[P_SN + n * 136 + m + 8]       = f32_tf32(tanh_ap(e[ni][2]));
                ps[P_SN + (n + 1) * 136 + m + 8] = f32_tf32(tanh_ap(e[ni][3]));
            }
        }
        __syncthreads();

        // GEMM2: acc[32c x 64m] += v * S^T  (8 k8 steps)
#pragma unroll
        for (int ks = 0; ks < 8; ks++) {
            const int k = ks * 8;
            uint32_t a[2][4], bb[8][2];
#pragma unroll
            for (int ct = 0; ct < 2; ct++) {
                int r = (cw + ct * 16 + lq) * 68 + k + lr;
                a[ct][0] = vsb[r];
                a[ct][1] = vsb[r + 8 * 68];
                a[ct][2] = vsb[r + 4];
                a[ct][3] = vsb[r + 8 * 68 + 4];
            }
#pragma unroll
            for (int mt = 0; mt < 8; mt++) {
                int c = mw + mt * 8 + lq;
                bb[mt][0] = ps[P_SN + (k + lr) * 136 + c];
                bb[mt][1] = ps[P_SN + (k + lr + 4) * 136 + c];
            }
#pragma unroll
            for (int ct = 0; ct < 2; ct++)
#pragma unroll
                for (int mt = 0; mt < 8; mt++)
                    mma_tf32(acc[ct][mt], a[ct], bb[mt][0], bb[mt][1]);
        }
    }

    // epilogue: out += gamma * acc
    const float g = gpa[0];
#pragma unroll
    for (int ct = 0; ct < 2; ct++) {
#pragma unroll
        for (int rr = 0; rr < 2; rr++) {
            int c = cw + ct * 16 + lq + rr * 8;
            float* row = &out[((b * C + c) << 12) + m0 + mw];
#pragma unroll
            for (int mt = 0; mt < 8; mt++) {
                int m = mt * 8 + lr * 2;
                float2* p = (float2*)&row[m];
                float2 cur = *p;
                cur.x += g * acc[ct][mt][rr * 2];
                cur.y += g * acc[ct][mt][rr * 2 + 1];
                *p = cur;
            }
        }
    }
}

// ---------------- launch ----------------
extern "C" void kernel_launch(void* const* d_in, const int* in_sizes, int n_in,
                              void* d_out, int out_size) {
    const float* x       = (const float*)d_in[0];
    const float* conv_w  = (const float*)d_in[1];
    const float* bn_g    = (const float*)d_in[2];
    const float* bn_b    = (const float*)d_in[3];
    const float* q_w     = (const float*)d_in[4];
    const float* q_b     = (const float*)d_in[5];
    const float* k_w     = (const float*)d_in[6];
    const float* k_b     = (const float*)d_in[7];
    const float* v_w     = (const float*)d_in[8];
    const float* v_b     = (const float*)d_in[9];
    const float* gca     = (const float*)d_in[10];
    const float* gpa     = (const float*)d_in[11];
    float* out = (float*)d_out;

    cudaFuncSetAttribute(conv_tc_kernel, cudaFuncAttributeMaxDynamicSharedMemorySize,
                         CONV_SMEM_WORDS * 4);
    cudaFuncSetAttribute(pam_mma_kernel, cudaFuncAttributeMaxDynamicSharedMemorySize,
                         P_WORDS * 4);

    wprep_kernel<<<1152, 256>>>(conv_w);
    conv_tc_kernel<<<dim3(64, B), 256, CONV_SMEM_WORDS * 4>>>(x);
    bnstats_kernel<<<C, 256>>>(bn_g, bn_b);
    bnrelu_kernel<<<2048, 256>>>(out);
    qkv_kernel<<<dim3(64, B), 256>>>(q_w, q_b, k_w, k_b, v_w, v_b);
    cam_energy_kernel<<<dim3(16, B), 256>>>();
    cam_attn_kernel<<<dim3(C, B), 128>>>();
    cam_out_kernel<<<dim3(64, B), 256>>>(gca, out);
    pam_mma_kernel<<<dim3(32, B), 256, P_WORDS * 4>>>(gpa, out);
}

// round 8
// speedup vs baseline: 2.8827x; 1.1946x over previous
#include <cuda_runtime.h>
#include <math.h>
#include <stdint.h>

// Problem constants
#define B   4
#define CIN 256
#define C   128
#define HW  64
#define N   4096          // HW*HW
#define CQK 16
#define ESPLIT 16         // CAM energy split-k slices

// ---------------- scratch (device globals; no allocation) ----------------
__device__ float g_y[B * C * N];        // conv out, then feat (in-place) : 8 MB
__device__ float g_scale[C];
__device__ float g_shift[C];
__device__ uint32_t g_q[B * CQK * N];   // tf32 bits
__device__ uint32_t g_k[B * CQK * N];   // tf32 bits
__device__ uint32_t g_v[B * C * N];     // tf32 bits : 8 MB
__device__ float g_e[B * C * C];        // CAM attn
__device__ float g_ep[ESPLIT * B * C * C];  // CAM energy partials : 4 MB
__device__ uint32_t g_w2hi[9 * 128 * 256];  // conv weights, tf32 hi, [off][co][ci]
__device__ uint32_t g_w2lo[9 * 128 * 256];  // tf32 residual

// ================= base-ISA tensor helpers (NO tcgen05 — plain sm_103) ======
__device__ __forceinline__ uint32_t f32_tf32(float f) {
    uint32_t r;
    asm("cvt.rna.tf32.f32 %0, %1;" : "=r"(r) : "f"(f));
    return r;
}
__device__ __forceinline__ float tanh_ap(float x) {
    float y;
    asm("tanh.approx.f32 %0, %1;" : "=f"(y) : "f"(x));
    return y;
}
// D += A(16x8 tf32) * B(8x8 tf32), fp32 accum
__device__ __forceinline__ void mma_tf32(float* d, const uint32_t* a, uint32_t b0, uint32_t b1) {
    asm volatile(
        "mma.sync.aligned.m16n8k8.row.col.f32.tf32.tf32.f32 "
        "{%0,%1,%2,%3}, {%4,%5,%6,%7}, {%8,%9}, {%0,%1,%2,%3};"
        : "+f"(d[0]), "+f"(d[1]), "+f"(d[2]), "+f"(d[3])
        : "r"(a[0]), "r"(a[1]), "r"(a[2]), "r"(a[3]), "r"(b0), "r"(b1));
}
__device__ __forceinline__ void cp16(uint32_t saddr, const void* g) {
    asm volatile("cp.async.cg.shared.global [%0], [%1], 16;" :: "r"(saddr), "l"(g));
}
__device__ __forceinline__ void cp_commit() {
    asm volatile("cp.async.commit_group;" ::: "memory");
}
template <int NN> __device__ __forceinline__ void cp_wait() {
    asm volatile("cp.async.wait_group %0;" :: "n"(NN) : "memory");
}

// ---------------- K0: weight prep: w -> tf32 hi/lo, [off][co][ci] ------------
__global__ void wprep_kernel(const float* __restrict__ w) {
    int i = blockIdx.x * 256 + threadIdx.x;
    if (i >= 9 * 128 * 256) return;
    int off = i >> 15;
    int rem = i & 32767;
    int co = rem >> 8, ci = rem & 255;
    float v = w[(co * 256 + ci) * 9 + off];
    uint32_t hi = f32_tf32(v);
    g_w2hi[i] = hi;
    g_w2lo[i] = f32_tf32(v - __uint_as_float(hi));
}

// ---------------- K1: 3x3 conv via mma.sync tf32 (3xTF32 split) --------------
#define XS_HI 0
#define XS_LO 6400
#define WS_HI 12800
#define WS_LO 17408
#define CONV_SMEM_WORDS 22016

__global__ __launch_bounds__(256)
void conv_tc_kernel(const float* __restrict__ x) {
    extern __shared__ uint32_t cs[];
    const int y = blockIdx.x, b = blockIdx.y;
    const int t = threadIdx.x;
    const int w = t >> 5, lane = t & 31;
    const int lq = lane >> 2, lr = lane & 3;
    const int cw = (w >> 1) * 32;
    const int pw = (w & 1) * 32;

    float acc[2][4][4];
#pragma unroll
    for (int ct = 0; ct < 2; ct++)
#pragma unroll
        for (int nt = 0; nt < 4; nt++)
#pragma unroll
            for (int i = 0; i < 4; i++) acc[ct][nt][i] = 0.f;

    for (int ci0 = 0; ci0 < CIN; ci0 += 32) {
        __syncthreads();
        for (int i = t; i < 32 * 198; i += 256) {
            int ci = i / 198, rem = i % 198;
            int yy = rem / 66, xx = rem % 66;
            int gy = y + yy - 1, gx = xx - 1;
            float v = 0.f;
            if (gy >= 0 && gy < HW && gx >= 0 && gx < HW)
                v = x[(((b * CIN + ci0 + ci) << 6) + gy) * 64 + gx];
            uint32_t hi = f32_tf32(v);
            int a = ci * 200 + yy * 66 + xx;
            cs[XS_HI + a] = hi;
            cs[XS_LO + a] = f32_tf32(v - __uint_as_float(hi));
        }

#pragma unroll 1
        for (int off = 0; off < 9; off++) {
            __syncthreads();
            {
                int base = (off << 15) + ci0;
#pragma unroll
                for (int p = 0; p < 16; p++) {
                    int i = t + p * 256;
                    int co = i >> 5, ci = i & 31;
                    int src = base + (co << 8) + ci;
                    cs[WS_HI + co * 36 + ci] = g_w2hi[src];
                    cs[WS_LO + co * 36 + ci] = g_w2lo[src];
                }
            }
            __syncthreads();
            const int ky = off / 3, kx = off % 3;
            const int xbase = ky * 66 + kx + pw;

#pragma unroll
            for (int ks = 0; ks < 4; ks++) {
                int k = ks * 8;
                uint32_t ahi[2][4], alo[2][4];
#pragma unroll
                for (int ct = 0; ct < 2; ct++) {
                    int r = (cw + ct * 16 + lq) * 36 + k + lr;
                    ahi[ct][0] = cs[WS_HI + r];
                    ahi[ct][1] = cs[WS_HI + r + 8 * 36];
                    ahi[ct][2] = cs[WS_HI + r + 4];
                    ahi[ct][3] = cs[WS_HI + r + 8 * 36 + 4];
                    alo[ct][0] = cs[WS_LO + r];
                    alo[ct][1] = cs[WS_LO + r + 8 * 36];
                    alo[ct][2] = cs[WS_LO + r + 4];
                    alo[ct][3] = cs[WS_LO + r + 8 * 36 + 4];
                }
#pragma unroll
                for (int nt = 0; nt < 4; nt++) {
                    int a0 = (k + lr) * 200 + xbase + nt * 8 + lq;
                    int a1 = a0 + 4 * 200;
                    uint32_t bh0 = cs[XS_HI + a0], bh1 = cs[XS_HI + a1];
                    uint32_t bl0 = cs[XS_LO + a0], bl1 = cs[XS_LO + a1];
#pragma unroll
                    for (int ct = 0; ct < 2; ct++) {
                        mma_tf32(acc[ct][nt], ahi[ct], bh0, bh1);
                        mma_tf32(acc[ct][nt], ahi[ct], bl0, bl1);
                        mma_tf32(acc[ct][nt], alo[ct], bh0, bh1);
                    }
                }
            }
        }
    }

#pragma unroll
    for (int ct = 0; ct < 2; ct++) {
#pragma unroll
        for (int rr = 0; rr < 2; rr++) {
            int co = cw + ct * 16 + lq + rr * 8;
            float* row = &g_y[((b * C + co) << 12) + (y << 6) + pw];
#pragma unroll
            for (int nt = 0; nt < 4; nt++) {
                int m = nt * 8 + lr * 2;
                float2 vv;
                vv.x = acc[ct][nt][rr * 2];
                vv.y = acc[ct][nt][rr * 2 + 1];
                *(float2*)&row[m] = vv;
            }
        }
    }
}

// ---------------- K2: per-channel batch stats ----------------
__global__ void bnstats_kernel(const float* __restrict__ gamma, const float* __restrict__ beta) {
    const int c = blockIdx.x;
    const int t = threadIdx.x;
    float s = 0.f, ss = 0.f;
    for (int i = t; i < B * N; i += 256) {
        int b = i >> 12, n = i & 4095;
        float v = g_y[((b * C + c) << 12) + n];
        s += v; ss += v * v;
    }
    __shared__ float r1[256], r2[256];
    r1[t] = s; r2[t] = ss;
    __syncthreads();
    for (int off = 128; off; off >>= 1) {
        if (t < off) { r1[t] += r1[t + off]; r2[t] += r2[t + off]; }
        __syncthreads();
    }
    if (t == 0) {
        const float inv = 1.f / (float)(B * N);
        float mean = r1[0] * inv;
        float var  = r2[0] * inv - mean * mean;
        float istd = rsqrtf(var + 1e-5f);
        float sc = gamma[c] * istd;
        g_scale[c] = sc;
        g_shift[c] = beta[c] - mean * sc;
    }
}

// ---------------- K3: BN + ReLU, d_out = 3*feat ----------------
__global__ void bnrelu_kernel(float* __restrict__ out) {
    const int total = B * C * N;
    for (int i = blockIdx.x * 256 + threadIdx.x; i < total; i += 2048 * 256) {
        int c = (i >> 12) & (C - 1);
        float v = fmaxf(g_y[i] * g_scale[c] + g_shift[c], 0.f);
        g_y[i] = v;
        out[i] = 3.f * v;
    }
}

// ---------------- K4: qkv via mma.sync tf32 ----------------------------------
// [q;k;v][160 x 64n] = W[160 x 128] @ f[128 x 64n] + bias.  grid (64, B), 320 thr.
#define QK_WS 0                       // W tf32 [o][c] pitch 132 : 21120 words
#define QK_FS 21120                   // f tf32 [c][n] pitch 72  : 9216 words
#define QK_BIAS 30336                 // 160 floats
#define QK_WORDS 30496

__global__ __launch_bounds__(320)
void qkv_mma_kernel(const float* __restrict__ qw, const float* __restrict__ qb,
                    const float* __restrict__ kw, const float* __restrict__ kb,
                    const float* __restrict__ vw, const float* __restrict__ vb) {
    extern __shared__ uint32_t qs_[];
    const int b = blockIdx.y, n0 = blockIdx.x * 64;
    const int t = threadIdx.x;
    const int w = t >> 5, lane = t & 31;
    const int lq = lane >> 2, lr = lane & 3;

    // stage W (tf32)
    for (int i = t; i < 160 * 128; i += 320) {
        int o = i >> 7, c = i & 127;
        float wv = (o < 16) ? qw[o * C + c]
                 : (o < 32) ? kw[(o - 16) * C + c]
                            : vw[(o - 32) * C + c];
        qs_[QK_WS + o * 132 + c] = f32_tf32(wv);
    }
    if (t < 160)
        ((float*)(qs_ + QK_BIAS))[t] = (t < 16) ? qb[t] : (t < 32 ? kb[t - 16] : vb[t - 32]);
    // stage f chunk (tf32)
    for (int i = t; i < 8192; i += 320) {
        int c = i >> 6, n = i & 63;
        qs_[QK_FS + c * 72 + n] = f32_tf32(g_y[((b * C + c) << 12) + n0 + n]);
    }
    __syncthreads();

    const int o0 = w * 16;
    float acc[8][4];
#pragma unroll
    for (int nt = 0; nt < 8; nt++)
#pragma unroll
        for (int i = 0; i < 4; i++) acc[nt][i] = 0.f;

#pragma unroll
    for (int ks = 0; ks < 16; ks++) {
        const int k = ks * 8;
        uint32_t a[4];
        {
            int r = (o0 + lq) * 132 + k + lr;
            a[0] = qs_[QK_WS + r];
            a[1] = qs_[QK_WS + r + 8 * 132];
            a[2] = qs_[QK_WS + r + 4];
            a[3] = qs_[QK_WS + r + 8 * 132 + 4];
        }
#pragma unroll
        for (int nt = 0; nt < 8; nt++) {
            uint32_t b0 = qs_[QK_FS + (k + lr) * 72 + nt * 8 + lq];
            uint32_t b1 = qs_[QK_FS + (k + lr + 4) * 72 + nt * 8 + lq];
            mma_tf32(acc[nt], a, b0, b1);
        }
    }

    const float* bias = (const float*)(qs_ + QK_BIAS);
#pragma unroll
    for (int rr = 0; rr < 2; rr++) {
        int o = o0 + lq + rr * 8;
        float bi = bias[o];
        uint32_t* dst = (o < 16) ? &g_q[((b * CQK + o) << 12) + n0]
                      : (o < 32) ? &g_k[((b * CQK + o - 16) << 12) + n0]
                                 : &g_v[((b * C + o - 32) << 12) + n0];
#pragma unroll
        for (int nt = 0; nt < 8; nt++) {
            int n = nt * 8 + lr * 2;
            uint2 u;
            u.x = f32_tf32(acc[nt][rr * 2] + bi);
            u.y = f32_tf32(acc[nt][rr * 2 + 1] + bi);
            *(uint2*)&dst[n] = u;
        }
    }
}

// ---------------- K5: CAM energy via mma.sync tf32, 3x split, split-k --------
// partial e[c][d] = sum_{n in slice} f[c][n] f[d][n].  grid (ESPLIT, B), 256 thr.
#define CE_FH 0
#define CE_FL 8704
#define CE_WORDS 17408

__global__ __launch_bounds__(256)
void cam_energy_mma_kernel() {
    extern __shared__ uint32_t es[];
    const int b = blockIdx.y, s = blockIdx.x;
    const int nbase = s * (N / ESPLIT);       // 256-wide slice
    const int t = threadIdx.x;
    const int w = t >> 5, lane = t & 31;
    const int lq = lane >> 2, lr = lane & 3;
    const int cw = (w & 3) * 32, dw = (w >> 2) * 64;

    float acc[2][8][4];
#pragma unroll
    for (int ct = 0; ct < 2; ct++)
#pragma unroll
        for (int dt = 0; dt < 8; dt++)
#pragma unroll
            for (int i = 0; i < 4; i++) acc[ct][dt][i] = 0.f;

    for (int it = 0; it < 4; it++) {
        const int n0 = nbase + it * 64;
        __syncthreads();
        for (int i = t; i < 8192; i += 256) {
            int c = i >> 6, n = i & 63;
            float v = g_y[((b * C + c) << 12) + n0 + n];
            uint32_t hi = f32_tf32(v);
            es[CE_FH + c * 68 + n] = hi;
            es[CE_FL + c * 68 + n] = f32_tf32(v - __uint_as_float(hi));
        }
        __syncthreads();

#pragma unroll
        for (int ks = 0; ks < 8; ks++) {
            const int k = ks * 8;
            uint32_t ah[2][4], al[2][4];
#pragma unroll
            for (int ct = 0; ct < 2; ct++) {
                int r = (cw + ct * 16 + lq) * 68 + k + lr;
                ah[ct][0] = es[CE_FH + r];
                ah[ct][1] = es[CE_FH + r + 8 * 68];
                ah[ct][2] = es[CE_FH + r + 4];
                ah[ct][3] = es[CE_FH + r + 8 * 68 + 4];
                al[ct][0] = es[CE_FL + r];
                al[ct][1] = es[CE_FL + r + 8 * 68];
                al[ct][2] = es[CE_FL + r + 4];
                al[ct][3] = es[CE_FL + r + 8 * 68 + 4];
            }
#pragma unroll
            for (int dt = 0; dt < 8; dt++) {
                int rb = (dw + dt * 8 + lq) * 68 + k + lr;
                uint32_t bh0 = es[CE_FH + rb], bh1 = es[CE_FH + rb + 4];
                uint32_t bl0 = es[CE_FL + rb], bl1 = es[CE_FL + rb + 4];
#pragma unroll
                for (int ct = 0; ct < 2; ct++) {
                    mma_tf32(acc[ct][dt], ah[ct], bh0, bh1);
                    mma_tf32(acc[ct][dt], ah[ct], bl0, bl1);
                    mma_tf32(acc[ct][dt], al[ct], bh0, bh1);
                }
            }
        }
    }

    float* ep = &g_ep[(s * B + b) << 14];
#pragma unroll
    for (int ct = 0; ct < 2; ct++) {
#pragma unroll
        for (int rr = 0; rr < 2; rr++) {
            int c = cw + ct * 16 + lq + rr * 8;
#pragma unroll
            for (int dt = 0; dt < 8; dt++) {
                int d = dw + dt * 8 + lr * 2;
                float2 vv;
                vv.x = acc[ct][dt][rr * 2];
                vv.y = acc[ct][dt][rr * 2 + 1];
                *(float2*)&ep[(c << 7) + d] = vv;
            }
        }
    }
}

// ---------------- K6: CAM reduce: sum partials, attn = tanh(rowmax - e) ------
__global__ void cam_reduce_kernel() {
    const int b = blockIdx.y, c = blockIdx.x, t = threadIdx.x; // 128 threads
    float e = 0.f;
#pragma unroll
    for (int s = 0; s < ESPLIT; s++)
        e += g_ep[((s * B + b) << 14) + (c << 7) + t];
    __shared__ float red[128];
    red[t] = e;
    __syncthreads();
    for (int off = 64; off; off >>= 1) {
        if (t < off) red[t] = fmaxf(red[t], red[t + off]);
        __syncthreads();
    }
    g_e[((b * C + c) << 7) + t] = tanhf(red[0] - e);
}

// ---------------- K7: CAM out via mma.sync tf32 ------------------------------
// out[128c x 128n] += gca * attn[128x128] @ f[128 x 128n-tile].  grid (32, B).
// 8 warps = 4(c-group of 32) x 2(n-half of 64); f staged full 128-wide.
#define CO_AS 0                        // attn tf32 [c][d] pitch 132 : 16896
#define CO_FS 16896                    // f tf32 [d][n] pitch 136    : 17408
#define CO_WORDS 34304

__global__ __launch_bounds__(256)
void cam_out_mma_kernel(const float* __restrict__ gca, float* __restrict__ out) {
    extern __shared__ uint32_t os_[];
    const int b = blockIdx.y, nb = blockIdx.x * 128;
    const int t = threadIdx.x;
    const int w = t >> 5, lane = t & 31;
    const int lq = lane >> 2, lr = lane & 3;
    const int cw = (w & 3) * 32, nw = (w >> 2) * 64;

    // stage attn (tf32)
    for (int i = t; i < 16384; i += 256) {
        int c = i >> 7, d = i & 127;
        os_[CO_AS + c * 132 + d] = f32_tf32(g_e[((b * C + c) << 7) + d]);
    }
    // stage f tile [d][128n] (tf32)
    for (int i = t; i < 16384; i += 256) {
        int d = i >> 7, n = i & 127;
        os_[CO_FS + d * 136 + n] = f32_tf32(g_y[((b * C + d) << 12) + nb + n]);
    }
    __syncthreads();

    float acc[2][8][4];
#pragma unroll
    for (int ct = 0; ct < 2; ct++)
#pragma unroll
        for (int nt = 0; nt < 8; nt++)
#pragma unroll
            for (int i = 0; i < 4; i++) acc[ct][nt][i] = 0.f;

#pragma unroll
    for (int ks = 0; ks < 16; ks++) {
        const int k = ks * 8;
        uint32_t a[2][4];
#pragma unroll
        for (int ct = 0; ct < 2; ct++) {
            int r = (cw + ct * 16 + lq) * 132 + k + lr;
            a[ct][0] = os_[CO_AS + r];
            a[ct][1] = os_[CO_AS + r + 8 * 132];
            a[ct][2] = os_[CO_AS + r + 4];
            a[ct][3] = os_[CO_AS + r + 8 * 132 + 4];
        }
#pragma unroll
        for (int nt = 0; nt < 8; nt++) {
            uint32_t b0 = os_[CO_FS + (k + lr) * 136 + nw + nt * 8 + lq];
            uint32_t b1 = os_[CO_FS + (k + lr + 4) * 136 + nw + nt * 8 + lq];
#pragma unroll
            for (int ct = 0; ct < 2; ct++)
                mma_tf32(acc[ct][nt], a[ct], b0, b1);
        }
    }

    const float g = gca[0];
#pragma unroll
    for (int ct = 0; ct < 2; ct++) {
#pragma unroll
        for (int rr = 0; rr < 2; rr++) {
            int c = cw + ct * 16 + lq + rr * 8;
            float* row = &out[((b * C + c) << 12) + nb + nw];
#pragma unroll
            for (int nt = 0; nt < 8; nt++) {
                int n = nt * 8 + lr * 2;
                float2* p = (float2*)&row[n];
                float2 cur = *p;
                cur.x += g * acc[ct][nt][rr * 2];
                cur.y += g * acc[ct][nt][rr * 2 + 1];
                *p = cur;
            }
        }
    }
}

// ---------------- K8: PAM: m-tile 128, n-chunk 64, cp.async dbuf -------------
#define P_QS 0                       // q^T [m][qc] 128x20
#define P_KS 2560                    // k [qc][n]  2 x 16x68
#define P_VS 4736                    // v [c][n]   2 x 128x68
#define P_SN 22144                   // S^T [n][m] 64x136
#define P_WORDS 30848

__global__ __launch_bounds__(256, 1)
void pam_mma_kernel(const float* __restrict__ gpa, float* __restrict__ out) {
    extern __shared__ uint32_t ps[];
    const int b = blockIdx.y, m0 = blockIdx.x * 128;
    const int t = threadIdx.x;
    const int w = t >> 5, lane = t & 31;
    const int lq = lane >> 2, lr = lane & 3;
    const uint32_t sbase = (uint32_t)__cvta_generic_to_shared(ps);

    for (int i = t; i < 2048; i += 256) {
        int qc = i >> 7, m = i & 127;
        ps[P_QS + m * 20 + qc] = g_q[((b * CQK + qc) << 12) + m0 + m];
    }

    const int krow = t >> 4, kc4 = (t & 15) * 4;
    const uint32_t kdst = sbase + (P_KS + krow * 68 + kc4) * 4;
    const uint32_t* kgsrc = &g_k[((b * CQK + krow) << 12) + kc4];
    const int vrow = t >> 4;
    const uint32_t vdst = sbase + (P_VS + vrow * 68 + kc4) * 4;
    const uint32_t* vgsrc = &g_v[((b * C + vrow) << 12) + kc4];

    cp16(kdst, kgsrc);
#pragma unroll
    for (int p = 0; p < 8; p++)
        cp16(vdst + p * 16 * 68 * 4, vgsrc + (p << 16));
    cp_commit();

    __syncthreads();   // q^T staging visible before fragment hoist

    uint32_t aq[2][4];
#pragma unroll
    for (int ks = 0; ks < 2; ks++) {
        int r = w * 16 + lq, c = ks * 8 + lr;
        aq[ks][0] = ps[P_QS + r * 20 + c];
        aq[ks][1] = ps[P_QS + (r + 8) * 20 + c];
        aq[ks][2] = ps[P_QS + r * 20 + c + 4];
        aq[ks][3] = ps[P_QS + (r + 8) * 20 + c + 4];
    }

    const int cw = (w & 3) * 32, mw = (w >> 2) * 64;
    float acc[2][8][4];
#pragma unroll
    for (int ct = 0; ct < 2; ct++)
#pragma unroll
        for (int mt = 0; mt < 8; mt++)
#pragma unroll
            for (int i = 0; i < 4; i++) acc[ct][mt][i] = 0.f;

#pragma unroll 1
    for (int ch = 0; ch < 64; ch++) {
        const int pb = ch & 1;
        const uint32_t* ksb = ps + P_KS + pb * (16 * 68);
        const uint32_t* vsb = ps + P_VS + pb * (128 * 68);

        __syncthreads();
        if (ch + 1 < 64) {
            const int n1 = (ch + 1) * 64;
            const int pn = pb ^ 1;
            cp16(kdst + pn * (16 * 68) * 4, kgsrc + n1);
#pragma unroll
            for (int p = 0; p < 8; p++)
                cp16(vdst + (pn * (128 * 68) + p * 16 * 68) * 4,
                     vgsrc + (p << 16) + n1);
            cp_commit();
            cp_wait<1>();
        } else {
            cp_wait<0>();
        }
        __syncthreads();

        float e[8][4];
#pragma unroll
        for (int ni = 0; ni < 8; ni++) {
#pragma unroll
            for (int i = 0; i < 4; i++) e[ni][i] = 0.f;
#pragma unroll
            for (int ks = 0; ks < 2; ks++) {
                uint32_t b0 = ksb[(ks * 8 + lr) * 68 + ni * 8 + lq];
                uint32_t b1 = ksb[(ks * 8 + lr + 4) * 68 + ni * 8 + lq];
                mma_tf32(e[ni], aq[ks], b0, b1);
            }
        }
        {
            int m = w * 16 + lq;
#pragma unroll
            for (int ni = 0; ni < 8; ni++) {
                int n = ni * 8 + lr * 2;
                ps[P_SN + n * 136 + m]           = f32_tf32(tanh_ap(e[ni][0]));
                ps[P_SN + (n + 1) * 136 + m]     = f32_tf32(tanh_ap(e[ni][1]));
                ps[P_SN + n * 136 + m + 8]       = f32_tf32(tanh_ap(e[ni][2]));
                ps[P_SN + (n + 1) * 136 + m + 8] = f32_tf32(tanh_ap(e[ni][3]));
            }
        }
        __syncthreads();

#pragma unroll
        for (int ks = 0; ks < 8; ks++) {
            const int k = ks * 8;
            uint32_t a[2][4], bb[8][2];
#pragma unroll
            for (int ct = 0; ct < 2; ct++) {
                int r = (cw + ct * 16 + lq) * 68 + k + lr;
                a[ct][0] = vsb[r];
                a[ct][1] = vsb[r + 8 * 68];
                a[ct][2] = vsb[r + 4];
                a[ct][3] = vsb[r + 8 * 68 + 4];
            }
#pragma unroll
            for (int mt = 0; mt < 8; mt++) {
                int c = mw + mt * 8 + lq;
                bb[mt][0] = ps[P_SN + (k + lr) * 136 + c];
                bb[mt][1] = ps[P_SN + (k + lr + 4) * 136 + c];
            }
#pragma unroll
            for (int ct = 0; ct < 2; ct++)
#pragma unroll
                for (int mt = 0; mt < 8; mt++)
                    mma_tf32(acc[ct][mt], a[ct], bb[mt][0], bb[mt][1]);
        }
    }

    const float g = gpa[0];
#pragma unroll
    for (int ct = 0; ct < 2; ct++) {
#pragma unroll
        for (int rr = 0; rr < 2; rr++) {
            int c = cw + ct * 16 + lq + rr * 8;
            float* row = &out[((b * C + c) << 12) + m0 + mw];
#pragma unroll
            for (int mt = 0; mt < 8; mt++) {
                int m = mt * 8 + lr * 2;
                float2* p = (float2*)&row[m];
                float2 cur = *p;
                cur.x += g * acc[ct][mt][rr * 2];
                cur.y += g * acc[ct][mt][rr * 2 + 1];
                *p = cur;
            }
        }
    }
}

// ---------------- launch ----------------
extern "C" void kernel_launch(void* const* d_in, const int* in_sizes, int n_in,
                              void* d_out, int out_size) {
    const float* x       = (const float*)d_in[0];
    const float* conv_w  = (const float*)d_in[1];
    const float* bn_g    = (const float*)d_in[2];
    const float* bn_b    = (const float*)d_in[3];
    const float* q_w     = (const float*)d_in[4];
    const float* q_b     = (const float*)d_in[5];
    const float* k_w     = (const float*)d_in[6];
    const float* k_b     = (const float*)d_in[7];
    const float* v_w     = (const float*)d_in[8];
    const float* v_b     = (const float*)d_in[9];
    const float* gca     = (const float*)d_in[10];
    const float* gpa     = (const float*)d_in[11];
    float* out = (float*)d_out;

    cudaFuncSetAttribute(conv_tc_kernel, cudaFuncAttributeMaxDynamicSharedMemorySize,
                         CONV_SMEM_WORDS * 4);
    cudaFuncSetAttribute(pam_mma_kernel, cudaFuncAttributeMaxDynamicSharedMemorySize,
                         P_WORDS * 4);
    cudaFuncSetAttribute(qkv_mma_kernel, cudaFuncAttributeMaxDynamicSharedMemorySize,
                         QK_WORDS * 4);
    cudaFuncSetAttribute(cam_energy_mma_kernel, cudaFuncAttributeMaxDynamicSharedMemorySize,
                         CE_WORDS * 4);
    cudaFuncSetAttribute(cam_out_mma_kernel, cudaFuncAttributeMaxDynamicSharedMemorySize,
                         CO_WORDS * 4);

    wprep_kernel<<<1152, 256>>>(conv_w);
    conv_tc_kernel<<<dim3(64, B), 256, CONV_SMEM_WORDS * 4>>>(x);
    bnstats_kernel<<<C, 256>>>(bn_g, bn_b);
    bnrelu_kernel<<<2048, 256>>>(out);
    qkv_mma_kernel<<<dim3(64, B), 320, QK_WORDS * 4>>>(q_w, q_b, k_w, k_b, v_w, v_b);
    cam_energy_mma_kernel<<<dim3(ESPLIT, B), 256, CE_WORDS * 4>>>();
    cam_reduce_kernel<<<dim3(C, B), 128>>>();
    cam_out_mma_kernel<<<dim3(32, B), 256, CO_WORDS * 4>>>(gca, out);
    pam_mma_kernel<<<dim3(32, B), 256, P_WORDS * 4>>>(gpa, out);
}